// round 2
// baseline (speedup 1.0000x reference)
#include <cuda_runtime.h>
#include <cuda_bf16.h>
#include <math.h>

// Problem constants
#define BB 4
#define SS 1024
#define SE 256
#define DD 1536
#define HH 24
#define HDIM 64
#define QLEN (SS + SE)            // 1280
#define KLEN (2*SS + SE)          // 2304

// ---------------- scratch (device globals; no allocs allowed) ----------------
__device__ float g_qtmp[BB*SS*DD];
__device__ float g_ktmp[BB*SS*DD];
__device__ float g_vtmp[BB*SS*DD];
__device__ float g_eqt[BB*SE*DD];
__device__ float g_ekt[BB*SE*DD];
__device__ float g_evt[BB*SE*DD];
__device__ float g_mq[BB*DD];
__device__ float g_sq[BB*DD];
__device__ float g_mk[BB*DD];
__device__ float g_sk[BB*DD];
__device__ float g_Q[BB*HH*QLEN*HDIM];
__device__ float g_K[BB*HH*KLEN*HDIM];
__device__ float g_V[BB*HH*KLEN*HDIM];
__device__ float g_ao[BB*QLEN*DD];

// ---------------- GEMM: C[M,N] = A[M,K] @ W[K,N] + bias, with A row remap ----
#define GBM 128
#define GBN 128
#define GBK 16

__global__ __launch_bounds__(256)
void gemm_bias_kernel(const float* __restrict__ A, const float* __restrict__ W,
                      const float* __restrict__ bias, float* __restrict__ C,
                      int M, int N, int K,
                      int rpb, int bstride, int roff)
{
    __shared__ float As[GBK][GBM];
    __shared__ float Bs[GBK][GBN];

    const int bx = blockIdx.x;     // N tile
    const int by = blockIdx.y;     // M tile
    const int tid = threadIdx.x;
    const int tx = tid % 16;
    const int ty = tid / 16;

    float acc[8][8];
#pragma unroll
    for (int i = 0; i < 8; i++)
#pragma unroll
        for (int j = 0; j < 8; j++) acc[i][j] = 0.f;

    const int a_r = tid / 4;            // 0..63
    const int a_c = (tid % 4) * 4;      // 0,4,8,12
    const int b_r = tid / 32;           // 0..7
    const int b_c = (tid % 32) * 4;

    for (int k0 = 0; k0 < K; k0 += GBK) {
#pragma unroll
        for (int i = 0; i < 2; i++) {
            int row = by*GBM + a_r + i*64;
            long prow = (long)(row / rpb) * bstride + roff + (row % rpb);
            float4 v = *(const float4*)(A + prow*K + k0 + a_c);
            As[a_c+0][a_r + i*64] = v.x;
            As[a_c+1][a_r + i*64] = v.y;
            As[a_c+2][a_r + i*64] = v.z;
            As[a_c+3][a_r + i*64] = v.w;
        }
#pragma unroll
        for (int i = 0; i < 2; i++) {
            int row = k0 + b_r + i*8;
            float4 v = *(const float4*)(W + (long)row*N + bx*GBN + b_c);
            *(float4*)&Bs[b_r + i*8][b_c] = v;
        }
        __syncthreads();

#pragma unroll
        for (int kk = 0; kk < GBK; kk++) {
            float af[8], bf[8];
            *(float4*)&af[0] = *(const float4*)&As[kk][ty*8];
            *(float4*)&af[4] = *(const float4*)&As[kk][ty*8+4];
            *(float4*)&bf[0] = *(const float4*)&Bs[kk][tx*8];
            *(float4*)&bf[4] = *(const float4*)&Bs[kk][tx*8+4];
#pragma unroll
            for (int i = 0; i < 8; i++)
#pragma unroll
                for (int j = 0; j < 8; j++)
                    acc[i][j] += af[i]*bf[j];
        }
        __syncthreads();
    }

#pragma unroll
    for (int i = 0; i < 8; i++) {
        long row = by*GBM + ty*8 + i;
#pragma unroll
        for (int j = 0; j < 8; j += 4) {
            int col = bx*GBN + tx*8 + j;
            float4 v;
            v.x = acc[i][j+0] + bias[col+0];
            v.y = acc[i][j+1] + bias[col+1];
            v.z = acc[i][j+2] + bias[col+2];
            v.w = acc[i][j+3] + bias[col+3];
            *(float4*)(C + row*N + col) = v;
        }
    }
}

// ---------------- AdaIN stats: mean/std over S per (b,d), ddof=1 -------------
__global__ __launch_bounds__(256)
void stats_kernel(const float* __restrict__ X, float* __restrict__ mean,
                  float* __restrict__ stdv)
{
    int d = blockIdx.x * 256 + threadIdx.x;   // 0..1535
    int b = blockIdx.y;
    const float* p = X + (long)b*SS*DD + d;
    float s = 0.f, ss = 0.f;
    for (int i = 0; i < SS; i++) {
        float v = p[(long)i*DD];
        s += v; ss += v*v;
    }
    float mu = s * (1.f/1024.f);
    float var = (ss - 1024.f*mu*mu) * (1.f/1023.f);
    mean[b*DD + d] = mu;
    stdv[b*DD + d] = sqrtf(var + 1e-5f);
}

// ---------------- Build Q/K/V head-layout buffers with AdaIN + style concat --
__global__ __launch_bounds__(256)
void build_kernel(const float* __restrict__ self_t, const float* __restrict__ enc_t,
                  const float* __restrict__ mean, const float* __restrict__ stdv,
                  float* __restrict__ Outbuf, int P, int has_mid, int do_adain)
{
    long idx = (long)blockIdx.x * blockDim.x + threadIdx.x;
    long total = (long)BB * HH * P * HDIM;
    if (idx >= total) return;
    int hd = (int)(idx % HDIM);
    long t = idx / HDIM;
    int p = (int)(t % P); t /= P;
    int h = (int)(t % HH);
    int b = (int)(t / HH);
    int d = h*HDIM + hd;
    int S2 = has_mid ? 2*SS : SS;
    float v;
    if (p < SS) {
        v = self_t[((long)b*SS + p)*DD + d];
        if (do_adain && (b & 1)) {
            int st = b - 1;   // STYLE_IDX = [0,0,2,2]
            v = (v - mean[b*DD+d]) / stdv[b*DD+d] * stdv[st*DD+d] + mean[st*DD+d];
        }
    } else if (p < S2) {
        int st = (b >> 1) << 1;   // style batch (0 or 2); adain is identity there
        v = self_t[((long)st*SS + (p - SS))*DD + d];
    } else {
        v = enc_t[((long)b*SE + (p - S2))*DD + d];
    }
    Outbuf[idx] = v;
}

// ---------------- Flash attention: 64x64 tiles, 4x4 microtiles ---------------
#define FA_BQ 64
#define FA_BK 64
#define FA_STR 65
#define FA_SMEM (4 * FA_BQ * FA_STR * 4)   // Qs + Ks + Vs + Ps  (66,560 B)

__global__ __launch_bounds__(256)
void flash_kernel(const float* __restrict__ Q, const float* __restrict__ Kt,
                  const float* __restrict__ Vt, float* __restrict__ Out)
{
    extern __shared__ float sm[];
    float* Qs = sm;
    float* Ks = Qs + FA_BQ*FA_STR;
    float* Vs = Ks + FA_BK*FA_STR;
    float* Ps = Vs + FA_BK*FA_STR;

    const int qt = blockIdx.x, h = blockIdx.y, b = blockIdx.z;
    const int tid = threadIdx.x;
    const int tr = tid / 16;    // 0..15 -> rows tr+16*i
    const int tc = tid % 16;    // 0..15 -> cols tc+16*j

    const float* Qbase = Q + (((long)b*HH + h)*QLEN + qt*FA_BQ) * HDIM;
    const float* Kbase = Kt + (((long)b*HH + h)*KLEN) * HDIM;
    const float* Vbase = Vt + (((long)b*HH + h)*KLEN) * HDIM;

    // load Q tile (64x64): 4 float4 per thread
#pragma unroll
    for (int i = 0; i < 4; i++) {
        int g = tid + 256*i;
        int row = g >> 4, c4 = (g & 15) << 2;
        float4 v = *(const float4*)(Qbase + row*HDIM + c4);
        Qs[row*FA_STR + c4+0] = v.x; Qs[row*FA_STR + c4+1] = v.y;
        Qs[row*FA_STR + c4+2] = v.z; Qs[row*FA_STR + c4+3] = v.w;
    }

    float m[4], l[4], o[4][4];
#pragma unroll
    for (int i = 0; i < 4; i++) {
        m[i] = -1e30f; l[i] = 0.f;
#pragma unroll
        for (int j = 0; j < 4; j++) o[i][j] = 0.f;
    }

    const float scale = 0.125f;   // 1/sqrt(64)

    for (int k0 = 0; k0 < KLEN; k0 += FA_BK) {
        __syncthreads();
#pragma unroll
        for (int i = 0; i < 4; i++) {
            int g = tid + 256*i;
            int row = g >> 4, c4 = (g & 15) << 2;
            float4 kv = *(const float4*)(Kbase + (long)(k0+row)*HDIM + c4);
            Ks[row*FA_STR + c4+0] = kv.x; Ks[row*FA_STR + c4+1] = kv.y;
            Ks[row*FA_STR + c4+2] = kv.z; Ks[row*FA_STR + c4+3] = kv.w;
            float4 vv = *(const float4*)(Vbase + (long)(k0+row)*HDIM + c4);
            Vs[row*FA_STR + c4+0] = vv.x; Vs[row*FA_STR + c4+1] = vv.y;
            Vs[row*FA_STR + c4+2] = vv.z; Vs[row*FA_STR + c4+3] = vv.w;
        }
        __syncthreads();

        float s[4][4];
#pragma unroll
        for (int i = 0; i < 4; i++)
#pragma unroll
            for (int j = 0; j < 4; j++) s[i][j] = 0.f;

#pragma unroll 8
        for (int d = 0; d < HDIM; d++) {
            float qv[4], kf[4];
#pragma unroll
            for (int i = 0; i < 4; i++) qv[i] = Qs[(tr + 16*i)*FA_STR + d];
#pragma unroll
            for (int j = 0; j < 4; j++) kf[j] = Ks[(tc + 16*j)*FA_STR + d];
#pragma unroll
            for (int i = 0; i < 4; i++)
#pragma unroll
                for (int j = 0; j < 4; j++)
                    s[i][j] += qv[i]*kf[j];
        }

#pragma unroll
        for (int i = 0; i < 4; i++) {
            float mm = -1e30f;
#pragma unroll
            for (int j = 0; j < 4; j++) { s[i][j] *= scale; mm = fmaxf(mm, s[i][j]); }
#pragma unroll
            for (int off = 1; off < 16; off <<= 1)
                mm = fmaxf(mm, __shfl_xor_sync(0xffffffffu, mm, off));
            float mnew = fmaxf(m[i], mm);
            float corr = __expf(m[i] - mnew);
            float psum = 0.f;
#pragma unroll
            for (int j = 0; j < 4; j++) {
                float p = __expf(s[i][j] - mnew);
                Ps[(tr + 16*i)*FA_STR + tc + 16*j] = p;
                psum += p;
            }
#pragma unroll
            for (int off = 1; off < 16; off <<= 1)
                psum += __shfl_xor_sync(0xffffffffu, psum, off);
            l[i] = l[i]*corr + psum;
            m[i] = mnew;
#pragma unroll
            for (int j = 0; j < 4; j++) o[i][j] *= corr;
        }
        __syncthreads();

#pragma unroll 8
        for (int kk = 0; kk < FA_BK; kk++) {
            float pv[4], vf[4];
#pragma unroll
            for (int i = 0; i < 4; i++) pv[i] = Ps[(tr + 16*i)*FA_STR + kk];
#pragma unroll
            for (int j = 0; j < 4; j++) vf[j] = Vs[kk*FA_STR + tc + 16*j];
#pragma unroll
            for (int i = 0; i < 4; i++)
#pragma unroll
                for (int j = 0; j < 4; j++)
                    o[i][j] += pv[i]*vf[j];
        }
    }

    // write to attn_out[b, qpos, h*64 + c], layout [B, QLEN, D]
#pragma unroll
    for (int i = 0; i < 4; i++) {
        int r = tr + 16*i;
        float inv = 1.f / l[i];
        long qpos = qt*FA_BQ + r;
#pragma unroll
        for (int j = 0; j < 4; j++) {
            int c = tc + 16*j;
            Out[((long)b*QLEN + qpos)*DD + h*HDIM + c] = o[i][j]*inv;
        }
    }
}

// ---------------- host ----------------
extern "C" void kernel_launch(void* const* d_in, const int* in_sizes, int n_in,
                              void* d_out, int out_size)
{
    const float* hs  = (const float*)d_in[0];
    const float* ehs = (const float*)d_in[1];
    const float* wq  = (const float*)d_in[2];  const float* bq  = (const float*)d_in[3];
    const float* wk  = (const float*)d_in[4];  const float* bk  = (const float*)d_in[5];
    const float* wv  = (const float*)d_in[6];  const float* bv  = (const float*)d_in[7];
    const float* awq = (const float*)d_in[8];  const float* abq = (const float*)d_in[9];
    const float* awk = (const float*)d_in[10]; const float* abk = (const float*)d_in[11];
    const float* awv = (const float*)d_in[12]; const float* abv = (const float*)d_in[13];
    const float* wo  = (const float*)d_in[14]; const float* bo  = (const float*)d_in[15];
    const float* wao = (const float*)d_in[16]; const float* bao = (const float*)d_in[17];
    float* out = (float*)d_out;

    float *qtmp, *ktmp, *vtmp, *eqt, *ekt, *evt, *mq, *sq, *mk, *sk, *Qb, *Kb, *Vb, *ao;
    cudaGetSymbolAddress((void**)&qtmp, g_qtmp);
    cudaGetSymbolAddress((void**)&ktmp, g_ktmp);
    cudaGetSymbolAddress((void**)&vtmp, g_vtmp);
    cudaGetSymbolAddress((void**)&eqt,  g_eqt);
    cudaGetSymbolAddress((void**)&ekt,  g_ekt);
    cudaGetSymbolAddress((void**)&evt,  g_evt);
    cudaGetSymbolAddress((void**)&mq,   g_mq);
    cudaGetSymbolAddress((void**)&sq,   g_sq);
    cudaGetSymbolAddress((void**)&mk,   g_mk);
    cudaGetSymbolAddress((void**)&sk,   g_sk);
    cudaGetSymbolAddress((void**)&Qb,   g_Q);
    cudaGetSymbolAddress((void**)&Kb,   g_K);
    cudaGetSymbolAddress((void**)&Vb,   g_V);
    cudaGetSymbolAddress((void**)&ao,   g_ao);

    const int M1 = BB*SS;   // 4096
    const int M2 = BB*SE;   // 1024
    dim3 gBig(DD/GBN, M1/GBM);   // (12, 32)
    dim3 gSml(DD/GBN, M2/GBM);   // (12, 8)

    // QKV projections
    gemm_bias_kernel<<<gBig, 256>>>(hs,  wq,  bq,  qtmp, M1, DD, DD, M1, 0, 0);
    gemm_bias_kernel<<<gBig, 256>>>(hs,  wk,  bk,  ktmp, M1, DD, DD, M1, 0, 0);
    gemm_bias_kernel<<<gBig, 256>>>(hs,  wv,  bv,  vtmp, M1, DD, DD, M1, 0, 0);
    gemm_bias_kernel<<<gSml, 256>>>(ehs, awq, abq, eqt,  M2, DD, DD, M2, 0, 0);
    gemm_bias_kernel<<<gSml, 256>>>(ehs, awk, abk, ekt,  M2, DD, DD, M2, 0, 0);
    gemm_bias_kernel<<<gSml, 256>>>(ehs, awv, abv, evt,  M2, DD, DD, M2, 0, 0);

    // AdaIN stats for q and k
    stats_kernel<<<dim3(DD/256, BB), 256>>>(qtmp, mq, sq);
    stats_kernel<<<dim3(DD/256, BB), 256>>>(ktmp, mk, sk);

    // Build Q/K/V in head layout with AdaIN + style concat
    {
        long tq = (long)BB*HH*QLEN*HDIM;
        long tk = (long)BB*HH*KLEN*HDIM;
        build_kernel<<<(unsigned)((tq + 255)/256), 256>>>(qtmp, eqt, mq, sq, Qb, QLEN, 0, 1);
        build_kernel<<<(unsigned)((tk + 255)/256), 256>>>(ktmp, ekt, mk, sk, Kb, KLEN, 1, 1);
        build_kernel<<<(unsigned)((tk + 255)/256), 256>>>(vtmp, evt, mk, sk, Vb, KLEN, 1, 0);
    }

    // Flash attention
    cudaFuncSetAttribute(flash_kernel, cudaFuncAttributeMaxDynamicSharedMemorySize, FA_SMEM);
    flash_kernel<<<dim3(QLEN/FA_BQ, HH, BB), 256, FA_SMEM>>>(Qb, Kb, Vb, ao);

    // Output projections: hid (rows 0..1023 of each batch) and enc (1024..1279)
    gemm_bias_kernel<<<gBig, 256>>>(ao, wo,  bo,  out,             M1, DD, DD, SS, QLEN, 0);
    gemm_bias_kernel<<<gSml, 256>>>(ao, wao, bao, out + (long)M1*DD, M2, DD, DD, SE, QLEN, SS);
}

// round 3
// speedup vs baseline: 1.5803x; 1.5803x over previous
#include <cuda_runtime.h>
#include <cuda_bf16.h>
#include <math.h>
#include <cstdint>

// Problem constants
#define BB 4
#define SS 1024
#define SE 256
#define DD 1536
#define HH 24
#define HDIM 64
#define QLEN (SS + SE)            // 1280
#define KLEN (2*SS + SE)          // 2304

// ---------------- scratch (device globals; no allocs allowed) ----------------
__device__ float g_qtmp[BB*SS*DD];
__device__ float g_ktmp[BB*SS*DD];
__device__ float g_vtmp[BB*SS*DD];
__device__ float g_eqt[BB*SE*DD];
__device__ float g_ekt[BB*SE*DD];
__device__ float g_evt[BB*SE*DD];
__device__ float g_mq[BB*DD];
__device__ float g_sq[BB*DD];
__device__ float g_mk[BB*DD];
__device__ float g_sk[BB*DD];
__device__ float g_Q[BB*HH*QLEN*HDIM];
__device__ float g_K[BB*HH*KLEN*HDIM];
__device__ float g_V[BB*HH*KLEN*HDIM];
__device__ float g_ao[BB*QLEN*DD];

// ---------------- tf32 MMA GEMM: C[M,N] = A[M,K] @ W[K,N] + bias -------------
// A rows can be remapped: prow = (row/rpb)*bstride + roff + row%rpb
#define TBM 128
#define TBN 128
#define TBK 32
#define A_LD 36                   // 32 + 4 pad (floats)
#define B_LD 132                  // 128 + 4 pad (floats)
#define STAGE_A (TBM*A_LD)        // 4608 floats
#define STAGE_B (TBK*B_LD)        // 4224 floats
#define STAGE_SZ (STAGE_A + STAGE_B)
#define MMA_SMEM (2*STAGE_SZ*4)   // 70656 bytes

__device__ __forceinline__ uint32_t f2tf(float f) {
    uint32_t r;
    asm("cvt.rna.tf32.f32 %0, %1;" : "=r"(r) : "f"(f));
    return r;
}

__device__ __forceinline__ void mma_tf32(float* c, const uint32_t* a,
                                         uint32_t b0, uint32_t b1) {
    asm volatile(
        "mma.sync.aligned.m16n8k8.row.col.f32.tf32.tf32.f32 "
        "{%0,%1,%2,%3}, {%4,%5,%6,%7}, {%8,%9}, {%0,%1,%2,%3};"
        : "+f"(c[0]), "+f"(c[1]), "+f"(c[2]), "+f"(c[3])
        : "r"(a[0]), "r"(a[1]), "r"(a[2]), "r"(a[3]), "r"(b0), "r"(b1));
}

__device__ __forceinline__ void cpasync16(uint32_t saddr, const void* gptr) {
    asm volatile("cp.async.ca.shared.global [%0], [%1], 16;"
                 :: "r"(saddr), "l"(gptr));
}

__global__ __launch_bounds__(256)
void gemm_tf32_kernel(const float* __restrict__ A, const float* __restrict__ W,
                      const float* __restrict__ bias, float* __restrict__ C,
                      int M, int N, int K,
                      int rpb, int bstride, int roff)
{
    extern __shared__ float smf[];

    const int tid  = threadIdx.x;
    const int lane = tid & 31;
    const int warp = tid >> 5;
    const int wm = (warp & 3) * 32;   // warp M offset (4 warps in M)
    const int wn = (warp >> 2) * 64;  // warp N offset (2 warps in N)
    const int mbase = blockIdx.y * TBM;
    const int nbase = blockIdx.x * TBN;

    // ---- precompute per-thread load pointers (invariant over K loop) ----
    // A: 1024 16B-chunks per tile, 4 per thread
    const float* aptr[4];
    uint32_t     sA[4];
    uint32_t     sB[4];
    const float* bptr[4];
#pragma unroll
    for (int i = 0; i < 4; i++) {
        int c = tid + 256*i;
        int row = c >> 3;             // 0..127
        int kc  = (c & 7) * 4;        // 0..28
        int grow = mbase + row;
        long prow = (long)(grow / rpb) * bstride + roff + (grow % rpb);
        aptr[i] = A + prow * K + kc;
        sA[i] = (uint32_t)__cvta_generic_to_shared(smf + row*A_LD + kc);

        int brow = c >> 5;            // 0..31
        int nc   = (c & 31) * 4;      // 0..124
        bptr[i] = W + (long)brow * N + nbase + nc;
        sB[i] = (uint32_t)__cvta_generic_to_shared(smf + STAGE_A + brow*B_LD + nc);
    }
    const uint32_t stage_bytes = STAGE_SZ * 4;

    float acc[2][8][4];
#pragma unroll
    for (int mi = 0; mi < 2; mi++)
#pragma unroll
        for (int nj = 0; nj < 8; nj++)
#pragma unroll
            for (int r = 0; r < 4; r++) acc[mi][nj][r] = 0.f;

    const int KT = K / TBK;

    // prologue: load tile 0 into stage 0
#pragma unroll
    for (int i = 0; i < 4; i++) {
        cpasync16(sA[i], aptr[i]);
        cpasync16(sB[i], bptr[i]);
    }
    asm volatile("cp.async.commit_group;");

    for (int t = 0; t < KT; t++) {
        // issue loads for tile t+1 into the other stage
        if (t + 1 < KT) {
            int k0 = (t + 1) * TBK;
            uint32_t soff = ((t + 1) & 1) * stage_bytes;
#pragma unroll
            for (int i = 0; i < 4; i++) {
                cpasync16(sA[i] + soff, aptr[i] + k0);
                cpasync16(sB[i] + soff, bptr[i] + (long)k0 * N);
            }
        }
        asm volatile("cp.async.commit_group;");
        asm volatile("cp.async.wait_group %0;" :: "n"(1));
        __syncthreads();

        const float* As = smf + (t & 1) * STAGE_SZ;
        const float* Bs = As + STAGE_A;

#pragma unroll
        for (int kk = 0; kk < 4; kk++) {
            const int k = kk * 8;
            uint32_t af[2][4];
#pragma unroll
            for (int mi = 0; mi < 2; mi++) {
                int r = wm + mi*16 + (lane >> 2);
                int cc = k + (lane & 3);
                af[mi][0] = f2tf(As[r*A_LD + cc]);
                af[mi][1] = f2tf(As[(r+8)*A_LD + cc]);
                af[mi][2] = f2tf(As[r*A_LD + cc + 4]);
                af[mi][3] = f2tf(As[(r+8)*A_LD + cc + 4]);
            }
#pragma unroll
            for (int nj = 0; nj < 8; nj++) {
                int col = wn + nj*8 + (lane >> 2);
                uint32_t b0 = f2tf(Bs[(k     + (lane & 3))*B_LD + col]);
                uint32_t b1 = f2tf(Bs[(k + 4 + (lane & 3))*B_LD + col]);
                mma_tf32(acc[0][nj], af[0], b0, b1);
                mma_tf32(acc[1][nj], af[1], b0, b1);
            }
        }
        __syncthreads();
    }

    // ---- epilogue: add bias, store ----
#pragma unroll
    for (int mi = 0; mi < 2; mi++) {
        int row0 = mbase + wm + mi*16 + (lane >> 2);
        int row1 = row0 + 8;
#pragma unroll
        for (int nj = 0; nj < 8; nj++) {
            int col = nbase + wn + nj*8 + (lane & 3)*2;
            float b0 = bias[col], b1 = bias[col + 1];
            float2 v0 = make_float2(acc[mi][nj][0] + b0, acc[mi][nj][1] + b1);
            float2 v1 = make_float2(acc[mi][nj][2] + b0, acc[mi][nj][3] + b1);
            *(float2*)(C + (long)row0*N + col) = v0;
            *(float2*)(C + (long)row1*N + col) = v1;
        }
    }
}

// ---------------- AdaIN stats: mean/std over S per (b,d), ddof=1 -------------
__global__ __launch_bounds__(256)
void stats_kernel(const float* __restrict__ X, float* __restrict__ mean,
                  float* __restrict__ stdv)
{
    int d = blockIdx.x * 256 + threadIdx.x;   // 0..1535
    int b = blockIdx.y;
    const float* p = X + (long)b*SS*DD + d;
    float s = 0.f, ss = 0.f;
    for (int i = 0; i < SS; i++) {
        float v = p[(long)i*DD];
        s += v; ss += v*v;
    }
    float mu = s * (1.f/1024.f);
    float var = (ss - 1024.f*mu*mu) * (1.f/1023.f);
    mean[b*DD + d] = mu;
    stdv[b*DD + d] = sqrtf(var + 1e-5f);
}

// ---------------- Build Q/K/V head-layout buffers with AdaIN + style concat --
__global__ __launch_bounds__(256)
void build_kernel(const float* __restrict__ self_t, const float* __restrict__ enc_t,
                  const float* __restrict__ mean, const float* __restrict__ stdv,
                  float* __restrict__ Outbuf, int P, int has_mid, int do_adain)
{
    long idx = (long)blockIdx.x * blockDim.x + threadIdx.x;
    long total = (long)BB * HH * P * HDIM;
    if (idx >= total) return;
    int hd = (int)(idx % HDIM);
    long t = idx / HDIM;
    int p = (int)(t % P); t /= P;
    int h = (int)(t % HH);
    int b = (int)(t / HH);
    int d = h*HDIM + hd;
    int S2 = has_mid ? 2*SS : SS;
    float v;
    if (p < SS) {
        v = self_t[((long)b*SS + p)*DD + d];
        if (do_adain && (b & 1)) {
            int st = b - 1;   // STYLE_IDX = [0,0,2,2]
            v = (v - mean[b*DD+d]) / stdv[b*DD+d] * stdv[st*DD+d] + mean[st*DD+d];
        }
    } else if (p < S2) {
        int st = (b >> 1) << 1;   // style batch (0 or 2); adain is identity there
        v = self_t[((long)st*SS + (p - SS))*DD + d];
    } else {
        v = enc_t[((long)b*SE + (p - S2))*DD + d];
    }
    Outbuf[idx] = v;
}

// ---------------- Flash attention: 64x64 tiles, 4x4 microtiles ---------------
#define FA_BQ 64
#define FA_BK 64
#define FA_STR 65
#define FA_SMEM (4 * FA_BQ * FA_STR * 4)   // Qs + Ks + Vs + Ps  (66,560 B)

__global__ __launch_bounds__(256)
void flash_kernel(const float* __restrict__ Q, const float* __restrict__ Kt,
                  const float* __restrict__ Vt, float* __restrict__ Out)
{
    extern __shared__ float sm[];
    float* Qs = sm;
    float* Ks = Qs + FA_BQ*FA_STR;
    float* Vs = Ks + FA_BK*FA_STR;
    float* Ps = Vs + FA_BK*FA_STR;

    const int qt = blockIdx.x, h = blockIdx.y, b = blockIdx.z;
    const int tid = threadIdx.x;
    const int tr = tid / 16;    // 0..15 -> rows tr+16*i
    const int tc = tid % 16;    // 0..15 -> cols tc+16*j

    const float* Qbase = Q + (((long)b*HH + h)*QLEN + qt*FA_BQ) * HDIM;
    const float* Kbase = Kt + (((long)b*HH + h)*KLEN) * HDIM;
    const float* Vbase = Vt + (((long)b*HH + h)*KLEN) * HDIM;

    // load Q tile (64x64): 4 float4 per thread
#pragma unroll
    for (int i = 0; i < 4; i++) {
        int g = tid + 256*i;
        int row = g >> 4, c4 = (g & 15) << 2;
        float4 v = *(const float4*)(Qbase + row*HDIM + c4);
        Qs[row*FA_STR + c4+0] = v.x; Qs[row*FA_STR + c4+1] = v.y;
        Qs[row*FA_STR + c4+2] = v.z; Qs[row*FA_STR + c4+3] = v.w;
    }

    float m[4], l[4], o[4][4];
#pragma unroll
    for (int i = 0; i < 4; i++) {
        m[i] = -1e30f; l[i] = 0.f;
#pragma unroll
        for (int j = 0; j < 4; j++) o[i][j] = 0.f;
    }

    const float scale = 0.125f;   // 1/sqrt(64)

    for (int k0 = 0; k0 < KLEN; k0 += FA_BK) {
        __syncthreads();
#pragma unroll
        for (int i = 0; i < 4; i++) {
            int g = tid + 256*i;
            int row = g >> 4, c4 = (g & 15) << 2;
            float4 kv = *(const float4*)(Kbase + (long)(k0+row)*HDIM + c4);
            Ks[row*FA_STR + c4+0] = kv.x; Ks[row*FA_STR + c4+1] = kv.y;
            Ks[row*FA_STR + c4+2] = kv.z; Ks[row*FA_STR + c4+3] = kv.w;
            float4 vv = *(const float4*)(Vbase + (long)(k0+row)*HDIM + c4);
            Vs[row*FA_STR + c4+0] = vv.x; Vs[row*FA_STR + c4+1] = vv.y;
            Vs[row*FA_STR + c4+2] = vv.z; Vs[row*FA_STR + c4+3] = vv.w;
        }
        __syncthreads();

        float s[4][4];
#pragma unroll
        for (int i = 0; i < 4; i++)
#pragma unroll
            for (int j = 0; j < 4; j++) s[i][j] = 0.f;

#pragma unroll 8
        for (int d = 0; d < HDIM; d++) {
            float qv[4], kf[4];
#pragma unroll
            for (int i = 0; i < 4; i++) qv[i] = Qs[(tr + 16*i)*FA_STR + d];
#pragma unroll
            for (int j = 0; j < 4; j++) kf[j] = Ks[(tc + 16*j)*FA_STR + d];
#pragma unroll
            for (int i = 0; i < 4; i++)
#pragma unroll
                for (int j = 0; j < 4; j++)
                    s[i][j] += qv[i]*kf[j];
        }

#pragma unroll
        for (int i = 0; i < 4; i++) {
            float mm = -1e30f;
#pragma unroll
            for (int j = 0; j < 4; j++) { s[i][j] *= scale; mm = fmaxf(mm, s[i][j]); }
#pragma unroll
            for (int off = 1; off < 16; off <<= 1)
                mm = fmaxf(mm, __shfl_xor_sync(0xffffffffu, mm, off));
            float mnew = fmaxf(m[i], mm);
            float corr = __expf(m[i] - mnew);
            float psum = 0.f;
#pragma unroll
            for (int j = 0; j < 4; j++) {
                float p = __expf(s[i][j] - mnew);
                Ps[(tr + 16*i)*FA_STR + tc + 16*j] = p;
                psum += p;
            }
#pragma unroll
            for (int off = 1; off < 16; off <<= 1)
                psum += __shfl_xor_sync(0xffffffffu, psum, off);
            l[i] = l[i]*corr + psum;
            m[i] = mnew;
#pragma unroll
            for (int j = 0; j < 4; j++) o[i][j] *= corr;
        }
        __syncthreads();

#pragma unroll 8
        for (int kk = 0; kk < FA_BK; kk++) {
            float pv[4], vf[4];
#pragma unroll
            for (int i = 0; i < 4; i++) pv[i] = Ps[(tr + 16*i)*FA_STR + kk];
#pragma unroll
            for (int j = 0; j < 4; j++) vf[j] = Vs[kk*FA_STR + tc + 16*j];
#pragma unroll
            for (int i = 0; i < 4; i++)
#pragma unroll
                for (int j = 0; j < 4; j++)
                    o[i][j] += pv[i]*vf[j];
        }
    }

    // write to attn_out[b, qpos, h*64 + c], layout [B, QLEN, D]
#pragma unroll
    for (int i = 0; i < 4; i++) {
        int r = tr + 16*i;
        float inv = 1.f / l[i];
        long qpos = qt*FA_BQ + r;
#pragma unroll
        for (int j = 0; j < 4; j++) {
            int c = tc + 16*j;
            Out[((long)b*QLEN + qpos)*DD + h*HDIM + c] = o[i][j]*inv;
        }
    }
}

// ---------------- host ----------------
extern "C" void kernel_launch(void* const* d_in, const int* in_sizes, int n_in,
                              void* d_out, int out_size)
{
    const float* hs  = (const float*)d_in[0];
    const float* ehs = (const float*)d_in[1];
    const float* wq  = (const float*)d_in[2];  const float* bq  = (const float*)d_in[3];
    const float* wk  = (const float*)d_in[4];  const float* bk  = (const float*)d_in[5];
    const float* wv  = (const float*)d_in[6];  const float* bv  = (const float*)d_in[7];
    const float* awq = (const float*)d_in[8];  const float* abq = (const float*)d_in[9];
    const float* awk = (const float*)d_in[10]; const float* abk = (const float*)d_in[11];
    const float* awv = (const float*)d_in[12]; const float* abv = (const float*)d_in[13];
    const float* wo  = (const float*)d_in[14]; const float* bo  = (const float*)d_in[15];
    const float* wao = (const float*)d_in[16]; const float* bao = (const float*)d_in[17];
    float* out = (float*)d_out;

    float *qtmp, *ktmp, *vtmp, *eqt, *ekt, *evt, *mq, *sq, *mk, *sk, *Qb, *Kb, *Vb, *ao;
    cudaGetSymbolAddress((void**)&qtmp, g_qtmp);
    cudaGetSymbolAddress((void**)&ktmp, g_ktmp);
    cudaGetSymbolAddress((void**)&vtmp, g_vtmp);
    cudaGetSymbolAddress((void**)&eqt,  g_eqt);
    cudaGetSymbolAddress((void**)&ekt,  g_ekt);
    cudaGetSymbolAddress((void**)&evt,  g_evt);
    cudaGetSymbolAddress((void**)&mq,   g_mq);
    cudaGetSymbolAddress((void**)&sq,   g_sq);
    cudaGetSymbolAddress((void**)&mk,   g_mk);
    cudaGetSymbolAddress((void**)&sk,   g_sk);
    cudaGetSymbolAddress((void**)&Qb,   g_Q);
    cudaGetSymbolAddress((void**)&Kb,   g_K);
    cudaGetSymbolAddress((void**)&Vb,   g_V);
    cudaGetSymbolAddress((void**)&ao,   g_ao);

    const int M1 = BB*SS;   // 4096
    const int M2 = BB*SE;   // 1024
    dim3 gBig(DD/TBN, M1/TBM);   // (12, 32)
    dim3 gSml(DD/TBN, M2/TBM);   // (12, 8)

    cudaFuncSetAttribute(gemm_tf32_kernel,
                         cudaFuncAttributeMaxDynamicSharedMemorySize, MMA_SMEM);

    // QKV projections
    gemm_tf32_kernel<<<gBig, 256, MMA_SMEM>>>(hs,  wq,  bq,  qtmp, M1, DD, DD, M1, 0, 0);
    gemm_tf32_kernel<<<gBig, 256, MMA_SMEM>>>(hs,  wk,  bk,  ktmp, M1, DD, DD, M1, 0, 0);
    gemm_tf32_kernel<<<gBig, 256, MMA_SMEM>>>(hs,  wv,  bv,  vtmp, M1, DD, DD, M1, 0, 0);
    gemm_tf32_kernel<<<gSml, 256, MMA_SMEM>>>(ehs, awq, abq, eqt,  M2, DD, DD, M2, 0, 0);
    gemm_tf32_kernel<<<gSml, 256, MMA_SMEM>>>(ehs, awk, abk, ekt,  M2, DD, DD, M2, 0, 0);
    gemm_tf32_kernel<<<gSml, 256, MMA_SMEM>>>(ehs, awv, abv, evt,  M2, DD, DD, M2, 0, 0);

    // AdaIN stats for q and k
    stats_kernel<<<dim3(DD/256, BB), 256>>>(qtmp, mq, sq);
    stats_kernel<<<dim3(DD/256, BB), 256>>>(ktmp, mk, sk);

    // Build Q/K/V in head layout with AdaIN + style concat
    {
        long tq = (long)BB*HH*QLEN*HDIM;
        long tk = (long)BB*HH*KLEN*HDIM;
        build_kernel<<<(unsigned)((tq + 255)/256), 256>>>(qtmp, eqt, mq, sq, Qb, QLEN, 0, 1);
        build_kernel<<<(unsigned)((tk + 255)/256), 256>>>(ktmp, ekt, mk, sk, Kb, KLEN, 1, 1);
        build_kernel<<<(unsigned)((tk + 255)/256), 256>>>(vtmp, evt, mk, sk, Vb, KLEN, 1, 0);
    }

    // Flash attention
    cudaFuncSetAttribute(flash_kernel, cudaFuncAttributeMaxDynamicSharedMemorySize, FA_SMEM);
    flash_kernel<<<dim3(QLEN/FA_BQ, HH, BB), 256, FA_SMEM>>>(Qb, Kb, Vb, ao);

    // Output projections: hid (rows 0..1023 of each batch) and enc (1024..1279)
    gemm_tf32_kernel<<<gBig, 256, MMA_SMEM>>>(ao, wo,  bo,  out,               M1, DD, DD, SS, QLEN, 0);
    gemm_tf32_kernel<<<gSml, 256, MMA_SMEM>>>(ao, wao, bao, out + (long)M1*DD, M2, DD, DD, SE, QLEN, SS);
}

// round 8
// speedup vs baseline: 3.0196x; 1.9108x over previous
#include <cuda_runtime.h>
#include <cuda_bf16.h>
#include <math.h>
#include <cstdint>

// Problem constants
#define BB 4
#define SS 1024
#define SE 256
#define DD 1536
#define HH 24
#define HDIM 64
#define QLEN (SS + SE)            // 1280
#define KLEN (2*SS + SE)          // 2304

// ---------------- scratch (device globals; no allocs allowed) ----------------
__device__ float g_qtmp[BB*SS*DD];
__device__ float g_ktmp[BB*SS*DD];
__device__ float g_vtmp[BB*SS*DD];
__device__ float g_eqt[BB*SE*DD];
__device__ float g_ekt[BB*SE*DD];
__device__ float g_evt[BB*SE*DD];
__device__ float g_mq[BB*DD];
__device__ float g_sq[BB*DD];
__device__ float g_mk[BB*DD];
__device__ float g_sk[BB*DD];
__device__ float g_Q[BB*HH*QLEN*HDIM];
__device__ float g_K[BB*HH*KLEN*HDIM];
__device__ float g_V[BB*HH*KLEN*HDIM];
__device__ float g_ao[BB*QLEN*DD];

// ---------------- common MMA helpers ----------------
__device__ __forceinline__ uint32_t f2tf(float f) {
    uint32_t r;
    asm("cvt.rna.tf32.f32 %0, %1;" : "=r"(r) : "f"(f));
    return r;
}

__device__ __forceinline__ void mma_tf32(float* c, const uint32_t* a,
                                         uint32_t b0, uint32_t b1) {
    asm volatile(
        "mma.sync.aligned.m16n8k8.row.col.f32.tf32.tf32.f32 "
        "{%0,%1,%2,%3}, {%4,%5,%6,%7}, {%8,%9}, {%0,%1,%2,%3};"
        : "+f"(c[0]), "+f"(c[1]), "+f"(c[2]), "+f"(c[3])
        : "r"(a[0]), "r"(a[1]), "r"(a[2]), "r"(a[3]), "r"(b0), "r"(b1));
}

__device__ __forceinline__ void cpasync16(uint32_t saddr, const void* gptr) {
    asm volatile("cp.async.ca.shared.global [%0], [%1], 16;"
                 :: "r"(saddr), "l"(gptr));
}

// ---------------- tf32 MMA GEMM: C[M,N] = A[M,K] @ W[K,N] + bias -------------
// A rows can be remapped: prow = (row/rpb)*bstride + roff + row%rpb
#define TBM 128
#define TBN 128
#define TBK 32
#define A_LD 36                   // 32 + 4 pad (floats)
#define B_LD 132                  // 128 + 4 pad (floats)
#define STAGE_A (TBM*A_LD)        // 4608 floats
#define STAGE_B (TBK*B_LD)        // 4224 floats
#define STAGE_SZ (STAGE_A + STAGE_B)
#define MMA_SMEM (2*STAGE_SZ*4)   // 70656 bytes

__global__ __launch_bounds__(256)
void gemm_tf32_kernel(const float* __restrict__ A, const float* __restrict__ W,
                      const float* __restrict__ bias, float* __restrict__ C,
                      int M, int N, int K,
                      int rpb, int bstride, int roff)
{
    extern __shared__ float smf[];

    const int tid  = threadIdx.x;
    const int lane = tid & 31;
    const int warp = tid >> 5;
    const int wm = (warp & 3) * 32;   // warp M offset (4 warps in M)
    const int wn = (warp >> 2) * 64;  // warp N offset (2 warps in N)
    const int mbase = blockIdx.y * TBM;
    const int nbase = blockIdx.x * TBN;

    const float* aptr[4];
    uint32_t     sA[4];
    uint32_t     sB[4];
    const float* bptr[4];
#pragma unroll
    for (int i = 0; i < 4; i++) {
        int c = tid + 256*i;
        int row = c >> 3;             // 0..127
        int kc  = (c & 7) * 4;        // 0..28
        int grow = mbase + row;
        long prow = (long)(grow / rpb) * bstride + roff + (grow % rpb);
        aptr[i] = A + prow * K + kc;
        sA[i] = (uint32_t)__cvta_generic_to_shared(smf + row*A_LD + kc);

        int brow = c >> 5;            // 0..31
        int nc   = (c & 31) * 4;      // 0..124
        bptr[i] = W + (long)brow * N + nbase + nc;
        sB[i] = (uint32_t)__cvta_generic_to_shared(smf + STAGE_A + brow*B_LD + nc);
    }
    const uint32_t stage_bytes = STAGE_SZ * 4;

    float acc[2][8][4];
#pragma unroll
    for (int mi = 0; mi < 2; mi++)
#pragma unroll
        for (int nj = 0; nj < 8; nj++)
#pragma unroll
            for (int r = 0; r < 4; r++) acc[mi][nj][r] = 0.f;

    const int KT = K / TBK;

#pragma unroll
    for (int i = 0; i < 4; i++) {
        cpasync16(sA[i], aptr[i]);
        cpasync16(sB[i], bptr[i]);
    }
    asm volatile("cp.async.commit_group;");

    for (int t = 0; t < KT; t++) {
        if (t + 1 < KT) {
            int k0 = (t + 1) * TBK;
            uint32_t soff = ((t + 1) & 1) * stage_bytes;
#pragma unroll
            for (int i = 0; i < 4; i++) {
                cpasync16(sA[i] + soff, aptr[i] + k0);
                cpasync16(sB[i] + soff, bptr[i] + (long)k0 * N);
            }
        }
        asm volatile("cp.async.commit_group;");
        asm volatile("cp.async.wait_group %0;" :: "n"(1));
        __syncthreads();

        const float* As = smf + (t & 1) * STAGE_SZ;
        const float* Bs = As + STAGE_A;

#pragma unroll
        for (int kk = 0; kk < 4; kk++) {
            const int k = kk * 8;
            uint32_t af[2][4];
#pragma unroll
            for (int mi = 0; mi < 2; mi++) {
                int r = wm + mi*16 + (lane >> 2);
                int cc = k + (lane & 3);
                af[mi][0] = f2tf(As[r*A_LD + cc]);
                af[mi][1] = f2tf(As[(r+8)*A_LD + cc]);
                af[mi][2] = f2tf(As[r*A_LD + cc + 4]);
                af[mi][3] = f2tf(As[(r+8)*A_LD + cc + 4]);
            }
#pragma unroll
            for (int nj = 0; nj < 8; nj++) {
                int col = wn + nj*8 + (lane >> 2);
                uint32_t b0 = f2tf(Bs[(k     + (lane & 3))*B_LD + col]);
                uint32_t b1 = f2tf(Bs[(k + 4 + (lane & 3))*B_LD + col]);
                mma_tf32(acc[0][nj], af[0], b0, b1);
                mma_tf32(acc[1][nj], af[1], b0, b1);
            }
        }
        __syncthreads();
    }

#pragma unroll
    for (int mi = 0; mi < 2; mi++) {
        int row0 = mbase + wm + mi*16 + (lane >> 2);
        int row1 = row0 + 8;
#pragma unroll
        for (int nj = 0; nj < 8; nj++) {
            int col = nbase + wn + nj*8 + (lane & 3)*2;
            float b0 = bias[col], b1 = bias[col + 1];
            float2 v0 = make_float2(acc[mi][nj][0] + b0, acc[mi][nj][1] + b1);
            float2 v1 = make_float2(acc[mi][nj][2] + b0, acc[mi][nj][3] + b1);
            *(float2*)(C + (long)row0*N + col) = v0;
            *(float2*)(C + (long)row1*N + col) = v1;
        }
    }
}

// ---------------- AdaIN stats: mean/std over S per (b,d), ddof=1 -------------
__global__ __launch_bounds__(256)
void stats_kernel(const float* __restrict__ X, float* __restrict__ mean,
                  float* __restrict__ stdv)
{
    int d = blockIdx.x * 256 + threadIdx.x;   // 0..1535
    int b = blockIdx.y;
    const float* p = X + (long)b*SS*DD + d;
    float s = 0.f, ss = 0.f;
    for (int i = 0; i < SS; i++) {
        float v = p[(long)i*DD];
        s += v; ss += v*v;
    }
    float mu = s * (1.f/1024.f);
    float var = (ss - 1024.f*mu*mu) * (1.f/1023.f);
    mean[b*DD + d] = mu;
    stdv[b*DD + d] = sqrtf(var + 1e-5f);
}

// ---------------- Build Q/K/V head-layout buffers with AdaIN + style concat --
__global__ __launch_bounds__(256)
void build_kernel(const float* __restrict__ self_t, const float* __restrict__ enc_t,
                  const float* __restrict__ mean, const float* __restrict__ stdv,
                  float* __restrict__ Outbuf, int P, int has_mid, int do_adain)
{
    long idx = (long)blockIdx.x * blockDim.x + threadIdx.x;
    long total = (long)BB * HH * P * HDIM;
    if (idx >= total) return;
    int hd = (int)(idx % HDIM);
    long t = idx / HDIM;
    int p = (int)(t % P); t /= P;
    int h = (int)(t % HH);
    int b = (int)(t / HH);
    int d = h*HDIM + hd;
    int S2 = has_mid ? 2*SS : SS;
    float v;
    if (p < SS) {
        v = self_t[((long)b*SS + p)*DD + d];
        if (do_adain && (b & 1)) {
            int st = b - 1;   // STYLE_IDX = [0,0,2,2]
            v = (v - mean[b*DD+d]) / stdv[b*DD+d] * stdv[st*DD+d] + mean[st*DD+d];
        }
    } else if (p < S2) {
        int st = (b >> 1) << 1;   // style batch (0 or 2); adain is identity there
        v = self_t[((long)st*SS + (p - SS))*DD + d];
    } else {
        v = enc_t[((long)b*SE + (p - S2))*DD + d];
    }
    Outbuf[idx] = v;
}

// ---------------- Flash attention on tf32 MMA -------------------------------
// BQ=128 (8 warps x m16), BK=64, HD=64.
// smem: QP (Q tile then per-warp P staging, ld 68) | Ks x2 (ld 68) | Vs x2 (ld 72)
#define FQ 128
#define FK 64
#define QLD 68
#define KLD 68
#define VLD 72
#define F_QP    (FQ*QLD)          // 8704 floats
#define F_KSTG  (FK*KLD)          // 4352 floats
#define F_VSTG  (FK*VLD)          // 4608 floats
#define F_SMEM  ((F_QP + 2*F_KSTG + 2*F_VSTG)*4)   // 106,496 bytes

__global__ __launch_bounds__(256)
void flash_tf32_kernel(const float* __restrict__ Q, const float* __restrict__ Kt,
                       const float* __restrict__ Vt, float* __restrict__ Out)
{
    extern __shared__ float sm[];
    float* QP = sm;
    float* KsB = sm + F_QP;
    float* VsB = KsB + 2*F_KSTG;

    const int qt = blockIdx.x, h = blockIdx.y, b = blockIdx.z;
    const int tid = threadIdx.x;
    const int lane = tid & 31;
    const int warp = tid >> 5;
    const int r = lane >> 2;       // 0..7
    const int c = lane & 3;        // 0..3
    const int mrow = warp*16 + r;  // this thread's low row in QP/P space

    const float* Qbase = Q + (((long)b*HH + h)*QLEN + qt*FQ) * HDIM;
    const float* Kbase = Kt + (((long)b*HH + h)*KLEN) * HDIM;
    const float* Vbase = Vt + (((long)b*HH + h)*KLEN) * HDIM;

    // ---- load Q tile 128x64 into smem ----
#pragma unroll
    for (int i = 0; i < 8; i++) {
        int g = tid + 256*i;              // 2048 float4 chunks
        int row = g >> 4, c4 = (g & 15) << 2;
        float4 v = *(const float4*)(Qbase + row*HDIM + c4);
        QP[row*QLD + c4+0] = v.x; QP[row*QLD + c4+1] = v.y;
        QP[row*QLD + c4+2] = v.z; QP[row*QLD + c4+3] = v.w;
    }
    __syncthreads();

    // ---- preconvert Q A-fragments to registers ----
    uint32_t qf[8][4];
#pragma unroll
    for (int kk = 0; kk < 8; kk++) {
        int k = kk*8 + c;
        qf[kk][0] = f2tf(QP[mrow*QLD + k]);
        qf[kk][1] = f2tf(QP[(mrow+8)*QLD + k]);
        qf[kk][2] = f2tf(QP[mrow*QLD + k + 4]);
        qf[kk][3] = f2tf(QP[(mrow+8)*QLD + k + 4]);
    }
    __syncthreads();   // everyone done reading Q before P staging overwrites

    // ---- cp.async prologue: KV tile 0 ----
    uint32_t sK[4], sV[4];
    const float* kp[4];
    const float* vp[4];
#pragma unroll
    for (int i = 0; i < 4; i++) {
        int g = tid + 256*i;               // 1024 chunks per tile
        int row = g >> 4, c4 = (g & 15) << 2;
        kp[i] = Kbase + (long)row*HDIM + c4;
        vp[i] = Vbase + (long)row*HDIM + c4;
        sK[i] = (uint32_t)__cvta_generic_to_shared(KsB + row*KLD + c4);
        sV[i] = (uint32_t)__cvta_generic_to_shared(VsB + row*VLD + c4);
    }
#pragma unroll
    for (int i = 0; i < 4; i++) {
        cpasync16(sK[i], kp[i]);
        cpasync16(sV[i], vp[i]);
    }
    asm volatile("cp.async.commit_group;");

    float m_lo = -1e30f, m_hi = -1e30f, l_lo = 0.f, l_hi = 0.f;
    float o[8][4];
#pragma unroll
    for (int nj = 0; nj < 8; nj++)
#pragma unroll
        for (int i = 0; i < 4; i++) o[nj][i] = 0.f;

    const float scale = 0.125f;   // 1/sqrt(64)
    const int NT = KLEN / FK;     // 36

    for (int t = 0; t < NT; t++) {
        if (t + 1 < NT) {
            long goff = (long)(t + 1) * FK * HDIM;
            uint32_t kso = ((t + 1) & 1) * (F_KSTG * 4);
            uint32_t vso = ((t + 1) & 1) * (F_VSTG * 4);
#pragma unroll
            for (int i = 0; i < 4; i++) {
                cpasync16(sK[i] + kso, kp[i] + goff);
                cpasync16(sV[i] + vso, vp[i] + goff);
            }
        }
        asm volatile("cp.async.commit_group;");
        asm volatile("cp.async.wait_group %0;" :: "n"(1));
        __syncthreads();

        const float* K0 = KsB + (t & 1) * F_KSTG;
        const float* V0 = VsB + (t & 1) * F_VSTG;

        // ---- S = Q K^T (m16 x n64 x k64) ----
        float s[8][4];
#pragma unroll
        for (int nj = 0; nj < 8; nj++)
#pragma unroll
            for (int i = 0; i < 4; i++) s[nj][i] = 0.f;

#pragma unroll
        for (int kk = 0; kk < 8; kk++) {
            const int kb = kk*8 + c;
#pragma unroll
            for (int nj = 0; nj < 8; nj++) {
                const float* kr = K0 + (nj*8 + r)*KLD + kb;
                uint32_t b0 = f2tf(kr[0]);
                uint32_t b1 = f2tf(kr[4]);
                mma_tf32(s[nj], qf[kk], b0, b1);
            }
        }

        // ---- online softmax ----
        float tmax_lo = -1e30f, tmax_hi = -1e30f;
#pragma unroll
        for (int nj = 0; nj < 8; nj++) {
            s[nj][0] *= scale; s[nj][1] *= scale;
            s[nj][2] *= scale; s[nj][3] *= scale;
            tmax_lo = fmaxf(tmax_lo, fmaxf(s[nj][0], s[nj][1]));
            tmax_hi = fmaxf(tmax_hi, fmaxf(s[nj][2], s[nj][3]));
        }
        tmax_lo = fmaxf(tmax_lo, __shfl_xor_sync(0xffffffffu, tmax_lo, 1));
        tmax_lo = fmaxf(tmax_lo, __shfl_xor_sync(0xffffffffu, tmax_lo, 2));
        tmax_hi = fmaxf(tmax_hi, __shfl_xor_sync(0xffffffffu, tmax_hi, 1));
        tmax_hi = fmaxf(tmax_hi, __shfl_xor_sync(0xffffffffu, tmax_hi, 2));

        float mn_lo = fmaxf(m_lo, tmax_lo);
        float mn_hi = fmaxf(m_hi, tmax_hi);
        float corr_lo = __expf(m_lo - mn_lo);
        float corr_hi = __expf(m_hi - mn_hi);

        float ps_lo = 0.f, ps_hi = 0.f;
#pragma unroll
        for (int nj = 0; nj < 8; nj++) {
            float p0 = __expf(s[nj][0] - mn_lo);
            float p1 = __expf(s[nj][1] - mn_lo);
            float p2 = __expf(s[nj][2] - mn_hi);
            float p3 = __expf(s[nj][3] - mn_hi);
            ps_lo += p0 + p1;
            ps_hi += p2 + p3;
            int col = nj*8 + 2*c;
            float2 v0; v0.x = __uint_as_float(f2tf(p0)); v0.y = __uint_as_float(f2tf(p1));
            float2 v1; v1.x = __uint_as_float(f2tf(p2)); v1.y = __uint_as_float(f2tf(p3));
            *(float2*)(QP + mrow*QLD + col) = v0;
            *(float2*)(QP + (mrow+8)*QLD + col) = v1;
        }
        ps_lo += __shfl_xor_sync(0xffffffffu, ps_lo, 1);
        ps_lo += __shfl_xor_sync(0xffffffffu, ps_lo, 2);
        ps_hi += __shfl_xor_sync(0xffffffffu, ps_hi, 1);
        ps_hi += __shfl_xor_sync(0xffffffffu, ps_hi, 2);

        l_lo = l_lo*corr_lo + ps_lo;  m_lo = mn_lo;
        l_hi = l_hi*corr_hi + ps_hi;  m_hi = mn_hi;
#pragma unroll
        for (int nj = 0; nj < 8; nj++) {
            o[nj][0] *= corr_lo; o[nj][1] *= corr_lo;
            o[nj][2] *= corr_hi; o[nj][3] *= corr_hi;
        }
        __syncwarp();

        // ---- O += P V (m16 x n64 x k64) ----
#pragma unroll
        for (int kk = 0; kk < 8; kk++) {
            uint32_t a[4];
            int k = kk*8 + c;
            a[0] = __float_as_uint(QP[mrow*QLD + k]);
            a[1] = __float_as_uint(QP[(mrow+8)*QLD + k]);
            a[2] = __float_as_uint(QP[mrow*QLD + k + 4]);
            a[3] = __float_as_uint(QP[(mrow+8)*QLD + k + 4]);
#pragma unroll
            for (int nj = 0; nj < 8; nj++) {
                uint32_t b0 = f2tf(V0[(kk*8 + c)*VLD + nj*8 + r]);
                uint32_t b1 = f2tf(V0[(kk*8 + c + 4)*VLD + nj*8 + r]);
                mma_tf32(o[nj], a, b0, b1);
            }
        }
        __syncwarp();
        __syncthreads();   // stage (t&1) free for the t+2 prefetch
    }

    // ---- normalize + write out [B, QLEN, D] ----
    float inv_lo = 1.f / l_lo;
    float inv_hi = 1.f / l_hi;
    long q0 = (long)qt*FQ + warp*16 + r;
    long base_lo = ((long)b*QLEN + q0)*DD + h*HDIM;
    long base_hi = base_lo + 8L*DD;
#pragma unroll
    for (int nj = 0; nj < 8; nj++) {
        int col = nj*8 + 2*c;
        float2 v0 = make_float2(o[nj][0]*inv_lo, o[nj][1]*inv_lo);
        float2 v1 = make_float2(o[nj][2]*inv_hi, o[nj][3]*inv_hi);
        *(float2*)(Out + base_lo + col) = v0;
        *(float2*)(Out + base_hi + col) = v1;
    }
}

// ---------------- host ----------------
extern "C" void kernel_launch(void* const* d_in, const int* in_sizes, int n_in,
                              void* d_out, int out_size)
{
    const float* hs  = (const float*)d_in[0];
    const float* ehs = (const float*)d_in[1];
    const float* wq  = (const float*)d_in[2];  const float* bq  = (const float*)d_in[3];
    const float* wk  = (const float*)d_in[4];  const float* bk  = (const float*)d_in[5];
    const float* wv  = (const float*)d_in[6];  const float* bv  = (const float*)d_in[7];
    const float* awq = (const float*)d_in[8];  const float* abq = (const float*)d_in[9];
    const float* awk = (const float*)d_in[10]; const float* abk = (const float*)d_in[11];
    const float* awv = (const float*)d_in[12]; const float* abv = (const float*)d_in[13];
    const float* wo  = (const float*)d_in[14]; const float* bo  = (const float*)d_in[15];
    const float* wao = (const float*)d_in[16]; const float* bao = (const float*)d_in[17];
    float* out = (float*)d_out;

    float *qtmp, *ktmp, *vtmp, *eqt, *ekt, *evt, *mq, *sq, *mk, *sk, *Qb, *Kb, *Vb, *ao;
    cudaGetSymbolAddress((void**)&qtmp, g_qtmp);
    cudaGetSymbolAddress((void**)&ktmp, g_ktmp);
    cudaGetSymbolAddress((void**)&vtmp, g_vtmp);
    cudaGetSymbolAddress((void**)&eqt,  g_eqt);
    cudaGetSymbolAddress((void**)&ekt,  g_ekt);
    cudaGetSymbolAddress((void**)&evt,  g_evt);
    cudaGetSymbolAddress((void**)&mq,   g_mq);
    cudaGetSymbolAddress((void**)&sq,   g_sq);
    cudaGetSymbolAddress((void**)&mk,   g_mk);
    cudaGetSymbolAddress((void**)&sk,   g_sk);
    cudaGetSymbolAddress((void**)&Qb,   g_Q);
    cudaGetSymbolAddress((void**)&Kb,   g_K);
    cudaGetSymbolAddress((void**)&Vb,   g_V);
    cudaGetSymbolAddress((void**)&ao,   g_ao);

    const int M1 = BB*SS;   // 4096
    const int M2 = BB*SE;   // 1024
    dim3 gBig(DD/TBN, M1/TBM);   // (12, 32)
    dim3 gSml(DD/TBN, M2/TBM);   // (12, 8)

    cudaFuncSetAttribute(gemm_tf32_kernel,
                         cudaFuncAttributeMaxDynamicSharedMemorySize, MMA_SMEM);
    cudaFuncSetAttribute(flash_tf32_kernel,
                         cudaFuncAttributeMaxDynamicSharedMemorySize, F_SMEM);

    // QKV projections
    gemm_tf32_kernel<<<gBig, 256, MMA_SMEM>>>(hs,  wq,  bq,  qtmp, M1, DD, DD, M1, 0, 0);
    gemm_tf32_kernel<<<gBig, 256, MMA_SMEM>>>(hs,  wk,  bk,  ktmp, M1, DD, DD, M1, 0, 0);
    gemm_tf32_kernel<<<gBig, 256, MMA_SMEM>>>(hs,  wv,  bv,  vtmp, M1, DD, DD, M1, 0, 0);
    gemm_tf32_kernel<<<gSml, 256, MMA_SMEM>>>(ehs, awq, abq, eqt,  M2, DD, DD, M2, 0, 0);
    gemm_tf32_kernel<<<gSml, 256, MMA_SMEM>>>(ehs, awk, abk, ekt,  M2, DD, DD, M2, 0, 0);
    gemm_tf32_kernel<<<gSml, 256, MMA_SMEM>>>(ehs, awv, abv, evt,  M2, DD, DD, M2, 0, 0);

    // AdaIN stats for q and k
    stats_kernel<<<dim3(DD/256, BB), 256>>>(qtmp, mq, sq);
    stats_kernel<<<dim3(DD/256, BB), 256>>>(ktmp, mk, sk);

    // Build Q/K/V in head layout with AdaIN + style concat
    {
        long tq = (long)BB*HH*QLEN*HDIM;
        long tk = (long)BB*HH*KLEN*HDIM;
        build_kernel<<<(unsigned)((tq + 255)/256), 256>>>(qtmp, eqt, mq, sq, Qb, QLEN, 0, 1);
        build_kernel<<<(unsigned)((tk + 255)/256), 256>>>(ktmp, ekt, mk, sk, Kb, KLEN, 1, 1);
        build_kernel<<<(unsigned)((tk + 255)/256), 256>>>(vtmp, evt, mk, sk, Vb, KLEN, 1, 0);
    }

    // Flash attention (tf32 tensor cores)
    flash_tf32_kernel<<<dim3(QLEN/FQ, HH, BB), 256, F_SMEM>>>(Qb, Kb, Vb, ao);

    // Output projections: hid (rows 0..1023 of each batch) and enc (1024..1279)
    gemm_tf32_kernel<<<gBig, 256, MMA_SMEM>>>(ao, wo,  bo,  out,               M1, DD, DD, SS, QLEN, 0);
    gemm_tf32_kernel<<<gSml, 256, MMA_SMEM>>>(ao, wao, bao, out + (long)M1*DD, M2, DD, DD, SE, QLEN, SS);
}

// round 11
// speedup vs baseline: 3.1451x; 1.0416x over previous
#include <cuda_runtime.h>
#include <cuda_bf16.h>
#include <math.h>
#include <cstdint>

// Problem constants
#define BB 4
#define SS 1024
#define SE 256
#define DD 1536
#define HH 24
#define HDIM 64
#define QLEN (SS + SE)            // 1280
#define KLEN (2*SS + SE)          // 2304
#define D3 (3*DD)                 // 4608

// ---------------- scratch (device globals; no allocs allowed) ----------------
__device__ float g_wqkv[DD*D3];       // [wq|wk|wv] tf32-rounded
__device__ float g_awqkv[DD*D3];
__device__ float g_wot[DD*DD];
__device__ float g_waot[DD*DD];
__device__ float g_hst[BB*SS*DD];     // hs tf32-rounded
__device__ float g_ehst[BB*SE*DD];
__device__ float g_bqkv[D3];
__device__ float g_abqkv[D3];
__device__ float g_qkv[BB*SS*D3];     // fused QKV projection of hs
__device__ float g_eqkv[BB*SE*D3];
__device__ float g_mq[BB*DD];
__device__ float g_sq[BB*DD];
__device__ float g_mk[BB*DD];
__device__ float g_sk[BB*DD];
__device__ float g_Q[BB*HH*QLEN*HDIM];     // d-permuted, tf32
__device__ float g_K[BB*HH*KLEN*HDIM];     // d-permuted, tf32
__device__ float g_Vt[BB*HH*HDIM*KLEN];    // transposed + k-permuted, tf32
__device__ float g_ao[BB*QLEN*DD];         // flash out, tf32-rounded

// ---------------- common helpers ----------------
__device__ __forceinline__ uint32_t f2tf(float f) {
    uint32_t r;
    asm("cvt.rna.tf32.f32 %0, %1;" : "=r"(r) : "f"(f));
    return r;
}
__device__ __forceinline__ float tfround(float f) { return __uint_as_float(f2tf(f)); }

__device__ __forceinline__ void mma_tf32(float* c, const uint32_t* a,
                                         uint32_t b0, uint32_t b1) {
    asm volatile(
        "mma.sync.aligned.m16n8k8.row.col.f32.tf32.tf32.f32 "
        "{%0,%1,%2,%3}, {%4,%5,%6,%7}, {%8,%9}, {%0,%1,%2,%3};"
        : "+f"(c[0]), "+f"(c[1]), "+f"(c[2]), "+f"(c[3])
        : "r"(a[0]), "r"(a[1]), "r"(a[2]), "r"(a[3]), "r"(b0), "r"(b1));
}

__device__ __forceinline__ void cpasync16(uint32_t saddr, const void* gptr) {
    asm volatile("cp.async.ca.shared.global [%0], [%1], 16;"
                 :: "r"(saddr), "l"(gptr));
}

// position of element k (0..63) within a permuted 64-float row; row enters mod 16
__device__ __forceinline__ int permpos(int k, int row) {
    int c   = k & 3;
    int rem = 2*(k>>3) + ((k>>2)&1);        // 0..15
    int unit = (c + (rem & ~3) + row) & 15; // (rem&~3) == 4*t
    return unit*4 + (rem & 3);
}

// ---------------- conversion kernels ----------------
__global__ __launch_bounds__(256)
void cvt4_kernel(const float4* __restrict__ s, float4* __restrict__ d, int n4)
{
    int i = blockIdx.x*256 + threadIdx.x;
    if (i >= n4) return;
    float4 v = s[i];
    v.x = tfround(v.x); v.y = tfround(v.y); v.z = tfround(v.z); v.w = tfround(v.w);
    d[i] = v;
}

__global__ __launch_bounds__(256)
void concat3_tf32_kernel(const float* __restrict__ a, const float* __restrict__ b,
                         const float* __restrict__ c, float* __restrict__ dst)
{
    long i = (long)blockIdx.x*256 + threadIdx.x;     // over DD*D3
    if (i >= (long)DD*D3) return;
    int row = (int)(i / D3), col = (int)(i % D3);
    float v;
    if (col < DD)           v = a[(long)row*DD + col];
    else if (col < 2*DD)    v = b[(long)row*DD + col - DD];
    else                    v = c[(long)row*DD + col - 2*DD];
    dst[i] = tfround(v);
}

__global__ __launch_bounds__(256)
void bias_concat_kernel(const float* __restrict__ a, const float* __restrict__ b,
                        const float* __restrict__ c, float* __restrict__ dst)
{
    int i = blockIdx.x*256 + threadIdx.x;
    if (i >= D3) return;
    dst[i] = i < DD ? a[i] : (i < 2*DD ? b[i-DD] : c[i-2*DD]);
}

// ---------------- tf32 MMA GEMM (operands pre-rounded): C = A@W + bias ------
#define TBM 128
#define TBN 128
#define TBK 32
#define A_LD 36
#define B_LD 132
#define STAGE_A (TBM*A_LD)
#define STAGE_B (TBK*B_LD)
#define STAGE_SZ (STAGE_A + STAGE_B)
#define MMA_SMEM (2*STAGE_SZ*4)

__global__ __launch_bounds__(256)
void gemm_tf32_kernel(const float* __restrict__ A, const float* __restrict__ W,
                      const float* __restrict__ bias, float* __restrict__ C,
                      int M, int N, int K,
                      int rpb, int bstride, int roff)
{
    extern __shared__ float smf[];

    const int tid  = threadIdx.x;
    const int lane = tid & 31;
    const int warp = tid >> 5;
    const int wm = (warp & 3) * 32;
    const int wn = (warp >> 2) * 64;
    const int mbase = blockIdx.y * TBM;
    const int nbase = blockIdx.x * TBN;

    const float* aptr[4];
    uint32_t     sA[4];
    uint32_t     sB[4];
    const float* bptr[4];
#pragma unroll
    for (int i = 0; i < 4; i++) {
        int c = tid + 256*i;
        int row = c >> 3;
        int kc  = (c & 7) * 4;
        int grow = mbase + row;
        long prow = (long)(grow / rpb) * bstride + roff + (grow % rpb);
        aptr[i] = A + prow * K + kc;
        sA[i] = (uint32_t)__cvta_generic_to_shared(smf + row*A_LD + kc);

        int brow = c >> 5;
        int nc   = (c & 31) * 4;
        bptr[i] = W + (long)brow * N + nbase + nc;
        sB[i] = (uint32_t)__cvta_generic_to_shared(smf + STAGE_A + brow*B_LD + nc);
    }
    const uint32_t stage_bytes = STAGE_SZ * 4;

    float acc[2][8][4];
#pragma unroll
    for (int mi = 0; mi < 2; mi++)
#pragma unroll
        for (int nj = 0; nj < 8; nj++)
#pragma unroll
            for (int r = 0; r < 4; r++) acc[mi][nj][r] = 0.f;

    const int KT = K / TBK;

#pragma unroll
    for (int i = 0; i < 4; i++) {
        cpasync16(sA[i], aptr[i]);
        cpasync16(sB[i], bptr[i]);
    }
    asm volatile("cp.async.commit_group;");

    for (int t = 0; t < KT; t++) {
        if (t + 1 < KT) {
            int k0 = (t + 1) * TBK;
            uint32_t soff = ((t + 1) & 1) * stage_bytes;
#pragma unroll
            for (int i = 0; i < 4; i++) {
                cpasync16(sA[i] + soff, aptr[i] + k0);
                cpasync16(sB[i] + soff, bptr[i] + (long)k0 * N);
            }
        }
        asm volatile("cp.async.commit_group;");
        asm volatile("cp.async.wait_group %0;" :: "n"(1));
        __syncthreads();

        const float* As = smf + (t & 1) * STAGE_SZ;
        const float* Bs = As + STAGE_A;

#pragma unroll
        for (int kk = 0; kk < 4; kk++) {
            const int k = kk * 8;
            uint32_t af[2][4];
#pragma unroll
            for (int mi = 0; mi < 2; mi++) {
                int r = wm + mi*16 + (lane >> 2);
                int cc = k + (lane & 3);
                af[mi][0] = __float_as_uint(As[r*A_LD + cc]);
                af[mi][1] = __float_as_uint(As[(r+8)*A_LD + cc]);
                af[mi][2] = __float_as_uint(As[r*A_LD + cc + 4]);
                af[mi][3] = __float_as_uint(As[(r+8)*A_LD + cc + 4]);
            }
#pragma unroll
            for (int nj = 0; nj < 8; nj++) {
                int col = wn + nj*8 + (lane >> 2);
                uint32_t b0 = __float_as_uint(Bs[(k     + (lane & 3))*B_LD + col]);
                uint32_t b1 = __float_as_uint(Bs[(k + 4 + (lane & 3))*B_LD + col]);
                mma_tf32(acc[0][nj], af[0], b0, b1);
                mma_tf32(acc[1][nj], af[1], b0, b1);
            }
        }
        __syncthreads();
    }

#pragma unroll
    for (int mi = 0; mi < 2; mi++) {
        int row0 = mbase + wm + mi*16 + (lane >> 2);
        int row1 = row0 + 8;
#pragma unroll
        for (int nj = 0; nj < 8; nj++) {
            int col = nbase + wn + nj*8 + (lane & 3)*2;
            float b0 = bias[col], b1 = bias[col + 1];
            float2 v0 = make_float2(acc[mi][nj][0] + b0, acc[mi][nj][1] + b1);
            float2 v1 = make_float2(acc[mi][nj][2] + b0, acc[mi][nj][3] + b1);
            *(float2*)(C + (long)row0*N + col) = v0;
            *(float2*)(C + (long)row1*N + col) = v1;
        }
    }
}

// ---------------- AdaIN stats over g_qkv columns ----------------
__global__ __launch_bounds__(256)
void stats_kernel(const float* __restrict__ X, float* __restrict__ mean,
                  float* __restrict__ stdv, int coff)
{
    int d = blockIdx.x * 256 + threadIdx.x;
    int b = blockIdx.y;
    const float* p = X + (long)b*SS*D3 + coff + d;
    float s = 0.f, ss = 0.f;
    for (int i = 0; i < SS; i++) {
        float v = p[(long)i*D3];
        s += v; ss += v*v;
    }
    float mu = s * (1.f/1024.f);
    float var = (ss - 1024.f*mu*mu) * (1.f/1023.f);
    mean[b*DD + d] = mu;
    stdv[b*DD + d] = sqrtf(var + 1e-5f);
}

// ---------------- build Q (permuted, tf32) ----------------
__global__ __launch_bounds__(256)
void build_q_kernel(const float* __restrict__ qkv, const float* __restrict__ eqkv,
                    const float* __restrict__ mean, const float* __restrict__ stdv,
                    float* __restrict__ Outbuf)
{
    long idx = (long)blockIdx.x * 256 + threadIdx.x;
    if (idx >= (long)BB*HH*QLEN*HDIM) return;
    int hd = (int)(idx & 63);
    long t = idx >> 6;
    int p = (int)(t % QLEN); t /= QLEN;
    int h = (int)(t % HH);
    int b = (int)(t / HH);
    int d = h*HDIM + hd;
    float v;
    if (p < SS) {
        v = qkv[((long)b*SS + p)*D3 + d];
        if (b & 1) {
            int st = b - 1;
            v = (v - mean[b*DD+d]) / stdv[b*DD+d] * stdv[st*DD+d] + mean[st*DD+d];
        }
    } else {
        v = eqkv[((long)b*SE + (p - SS))*D3 + d];
    }
    Outbuf[(((long)b*HH + h)*QLEN + p)*64 + permpos(hd, p)] = tfround(v);
}

// ---------------- build K (permuted, tf32, style concat + adain) -------------
__global__ __launch_bounds__(256)
void build_k_kernel(const float* __restrict__ qkv, const float* __restrict__ eqkv,
                    const float* __restrict__ mean, const float* __restrict__ stdv,
                    float* __restrict__ Outbuf)
{
    long idx = (long)blockIdx.x * 256 + threadIdx.x;
    if (idx >= (long)BB*HH*KLEN*HDIM) return;
    int hd = (int)(idx & 63);
    long t = idx >> 6;
    int p = (int)(t % KLEN); t /= KLEN;
    int h = (int)(t % HH);
    int b = (int)(t / HH);
    int d = h*HDIM + hd;
    float v;
    if (p < SS) {
        v = qkv[((long)b*SS + p)*D3 + DD + d];
        if (b & 1) {
            int st = b - 1;
            v = (v - mean[b*DD+d]) / stdv[b*DD+d] * stdv[st*DD+d] + mean[st*DD+d];
        }
    } else if (p < 2*SS) {
        int st = (b >> 1) << 1;
        v = qkv[((long)st*SS + (p - SS))*D3 + DD + d];
    } else {
        v = eqkv[((long)b*SE + (p - 2*SS))*D3 + DD + d];
    }
    Outbuf[(((long)b*HH + h)*KLEN + p)*64 + permpos(hd, p)] = tfround(v);
}

// ---------------- build V^T (transposed, permuted, tf32) --------------------
__global__ __launch_bounds__(256)
void build_v_kernel(const float* __restrict__ qkv, const float* __restrict__ eqkv,
                    float* __restrict__ Outbuf)
{
    long idx = (long)blockIdx.x * 256 + threadIdx.x;   // p fastest
    if (idx >= (long)BB*HH*HDIM*KLEN) return;
    int p = (int)(idx % KLEN);
    long t = idx / KLEN;
    int hd = (int)(t & 63); t >>= 6;
    int h = (int)(t % HH);
    int b = (int)(t / HH);
    int d = h*HDIM + hd;
    float v;
    if (p < SS) {
        v = qkv[((long)b*SS + p)*D3 + 2*DD + d];
    } else if (p < 2*SS) {
        int st = (b >> 1) << 1;
        v = qkv[((long)st*SS + (p - SS))*D3 + 2*DD + d];
    } else {
        v = eqkv[((long)b*SE + (p - 2*SS))*D3 + 2*DD + d];
    }
    Outbuf[(((long)b*HH + h)*HDIM + hd)*(long)KLEN + (p & ~63) + permpos(p & 63, hd)]
        = tfround(v);
}

// ---------------- Flash attention: vectorized tf32 MMA ----------------------
#define FKLD 76
#define F_QS  (128*FKLD)          // 9728 floats (Q tile, then P staging)
#define F_KST (64*FKLD)           // 4864 floats per stage
#define F_SMEM2 ((F_QS + 4*F_KST)*4)   // 116,736 bytes

__global__ __launch_bounds__(256)
void flash2_kernel(const float* __restrict__ Qg, const float* __restrict__ Kg,
                   const float* __restrict__ Vg, float* __restrict__ Out)
{
    extern __shared__ float sm[];
    float* Qs  = sm;                 // Q tile then P staging
    float* Kst = sm + F_QS;
    float* Vst = Kst + 2*F_KST;

    const int qt = blockIdx.x, h = blockIdx.y, b = blockIdx.z;
    const int tid = threadIdx.x, lane = tid & 31, warp = tid >> 5;
    const int r = lane >> 2, c = lane & 3;
    const int mrow = warp*16 + r;

    const float* Qbase = Qg + (((long)b*HH + h)*QLEN + qt*128) * 64;
    const float* Kbase = Kg + ((long)b*HH + h) * KLEN * 64;
    const float* Vbase = Vg + ((long)b*HH + h) * HDIM * (long)KLEN;

    // ---- Q tile: 2048 16B chunks ----
#pragma unroll
    for (int i = 0; i < 8; i++) {
        int g = tid + 256*i;
        int row = g >> 4, u = g & 15;
        cpasync16((uint32_t)__cvta_generic_to_shared(Qs + row*FKLD + u*4),
                  Qbase + row*64 + u*4);
    }
    asm volatile("cp.async.commit_group;");

    // ---- KV tile 0 ----
    const float* kp[4]; const float* vp[4];
    uint32_t sK[4], sV[4];
#pragma unroll
    for (int i = 0; i < 4; i++) {
        int g = tid + 256*i;
        int row = g >> 4, u = g & 15;
        kp[i] = Kbase + row*64 + u*4;
        vp[i] = Vbase + (long)row*KLEN + u*4;
        sK[i] = (uint32_t)__cvta_generic_to_shared(Kst + row*FKLD + u*4);
        sV[i] = (uint32_t)__cvta_generic_to_shared(Vst + row*FKLD + u*4);
        cpasync16(sK[i], kp[i]);
        cpasync16(sV[i], vp[i]);
    }
    asm volatile("cp.async.commit_group;");
    asm volatile("cp.async.wait_group 1;");   // Q arrived
    __syncthreads();

    // ---- extract Q A-fragments (already tf32 bit patterns) ----
    uint32_t qf[8][4];
#pragma unroll
    for (int t = 0; t < 4; t++) {
        int u0 = (c + 4*t + mrow) & 15;
        int u1 = (c + 4*t + mrow + 8) & 15;
        float4 f0 = *(const float4*)(Qs + mrow*FKLD + u0*4);
        float4 f1 = *(const float4*)(Qs + (mrow+8)*FKLD + u1*4);
        qf[2*t][0]   = __float_as_uint(f0.x); qf[2*t][1]   = __float_as_uint(f1.x);
        qf[2*t][2]   = __float_as_uint(f0.y); qf[2*t][3]   = __float_as_uint(f1.y);
        qf[2*t+1][0] = __float_as_uint(f0.z); qf[2*t+1][1] = __float_as_uint(f1.z);
        qf[2*t+1][2] = __float_as_uint(f0.w); qf[2*t+1][3] = __float_as_uint(f1.w);
    }
    __syncthreads();   // all warps done reading Q; Qs becomes P staging

    float m_lo = -1e30f, m_hi = -1e30f, l_lo = 0.f, l_hi = 0.f;
    float o[8][4];
#pragma unroll
    for (int nj = 0; nj < 8; nj++)
#pragma unroll
        for (int i = 0; i < 4; i++) o[nj][i] = 0.f;

    const float scale = 0.125f;
    const int NT = KLEN / 64;     // 36

    for (int tt = 0; tt < NT; tt++) {
        if (tt + 1 < NT) {
            uint32_t so = ((tt + 1) & 1) * (F_KST * 4);
            long kgo = (long)(tt + 1) * 4096;
            long vgo = (long)(tt + 1) * 64;
#pragma unroll
            for (int i = 0; i < 4; i++) {
                cpasync16(sK[i] + so, kp[i] + kgo);
                cpasync16(sV[i] + so, vp[i] + vgo);
            }
        }
        asm volatile("cp.async.commit_group;");
        asm volatile("cp.async.wait_group %0;" :: "n"(1));
        __syncthreads();

        const float* K0 = Kst + (tt & 1) * F_KST;
        const float* V0 = Vst + (tt & 1) * F_KST;

        // ---- S = Q K^T ----
        float s[8][4];
#pragma unroll
        for (int nj = 0; nj < 8; nj++)
#pragma unroll
            for (int i = 0; i < 4; i++) s[nj][i] = 0.f;

#pragma unroll
        for (int t = 0; t < 4; t++) {
#pragma unroll
            for (int nj = 0; nj < 8; nj++) {
                int row = nj*8 + r;
                int u = (c + 4*t + row) & 15;
                float4 f = *(const float4*)(K0 + row*FKLD + u*4);
                mma_tf32(s[nj], qf[2*t],   __float_as_uint(f.x), __float_as_uint(f.y));
                mma_tf32(s[nj], qf[2*t+1], __float_as_uint(f.z), __float_as_uint(f.w));
            }
        }

        // ---- online softmax ----
        float tmax_lo = -1e30f, tmax_hi = -1e30f;
#pragma unroll
        for (int nj = 0; nj < 8; nj++) {
            s[nj][0] *= scale; s[nj][1] *= scale;
            s[nj][2] *= scale; s[nj][3] *= scale;
            tmax_lo = fmaxf(tmax_lo, fmaxf(s[nj][0], s[nj][1]));
            tmax_hi = fmaxf(tmax_hi, fmaxf(s[nj][2], s[nj][3]));
        }
        tmax_lo = fmaxf(tmax_lo, __shfl_xor_sync(0xffffffffu, tmax_lo, 1));
        tmax_lo = fmaxf(tmax_lo, __shfl_xor_sync(0xffffffffu, tmax_lo, 2));
        tmax_hi = fmaxf(tmax_hi, __shfl_xor_sync(0xffffffffu, tmax_hi, 1));
        tmax_hi = fmaxf(tmax_hi, __shfl_xor_sync(0xffffffffu, tmax_hi, 2));

        float mn_lo = fmaxf(m_lo, tmax_lo);
        float mn_hi = fmaxf(m_hi, tmax_hi);
        float corr_lo = __expf(m_lo - mn_lo);
        float corr_hi = __expf(m_hi - mn_hi);

        float ps_lo = 0.f, ps_hi = 0.f;
#pragma unroll
        for (int nj = 0; nj < 8; nj++) {
            float p0 = __expf(s[nj][0] - mn_lo);
            float p1 = __expf(s[nj][1] - mn_lo);
            float p2 = __expf(s[nj][2] - mn_hi);
            float p3 = __expf(s[nj][3] - mn_hi);
            ps_lo += p0 + p1;
            ps_hi += p2 + p3;
            int col = nj*8 + 2*c;
            float2 v0; v0.x = __uint_as_float(f2tf(p0)); v0.y = __uint_as_float(f2tf(p1));
            float2 v1; v1.x = __uint_as_float(f2tf(p2)); v1.y = __uint_as_float(f2tf(p3));
            *(float2*)(Qs + mrow*FKLD + col) = v0;
            *(float2*)(Qs + (mrow+8)*FKLD + col) = v1;
        }
        ps_lo += __shfl_xor_sync(0xffffffffu, ps_lo, 1);
        ps_lo += __shfl_xor_sync(0xffffffffu, ps_lo, 2);
        ps_hi += __shfl_xor_sync(0xffffffffu, ps_hi, 1);
        ps_hi += __shfl_xor_sync(0xffffffffu, ps_hi, 2);

        l_lo = l_lo*corr_lo + ps_lo;  m_lo = mn_lo;
        l_hi = l_hi*corr_hi + ps_hi;  m_hi = mn_hi;
#pragma unroll
        for (int nj = 0; nj < 8; nj++) {
            o[nj][0] *= corr_lo; o[nj][1] *= corr_lo;
            o[nj][2] *= corr_hi; o[nj][3] *= corr_hi;
        }
        __syncwarp();

        // ---- O += P V ----
#pragma unroll
        for (int t = 0; t < 4; t++) {
            int k0 = 16*t + c;
            int k1 = k0 + 8;
            uint32_t a0[4], a1[4];
            a0[0] = __float_as_uint(Qs[mrow*FKLD + k0]);
            a0[1] = __float_as_uint(Qs[(mrow+8)*FKLD + k0]);
            a0[2] = __float_as_uint(Qs[mrow*FKLD + k0 + 4]);
            a0[3] = __float_as_uint(Qs[(mrow+8)*FKLD + k0 + 4]);
            a1[0] = __float_as_uint(Qs[mrow*FKLD + k1]);
            a1[1] = __float_as_uint(Qs[(mrow+8)*FKLD + k1]);
            a1[2] = __float_as_uint(Qs[mrow*FKLD + k1 + 4]);
            a1[3] = __float_as_uint(Qs[(mrow+8)*FKLD + k1 + 4]);
#pragma unroll
            for (int nj = 0; nj < 8; nj++) {
                int row = nj*8 + r;
                int u = (c + 4*t + row) & 15;
                float4 f = *(const float4*)(V0 + row*FKLD + u*4);
                mma_tf32(o[nj], a0, __float_as_uint(f.x), __float_as_uint(f.y));
                mma_tf32(o[nj], a1, __float_as_uint(f.z), __float_as_uint(f.w));
            }
        }
        __syncwarp();
        __syncthreads();   // P staging + stage (tt&1) free for reuse
    }

    // ---- normalize + write out [B, QLEN, D], tf32-rounded for out-proj ----
    float inv_lo = 1.f / l_lo;
    float inv_hi = 1.f / l_hi;
    long q0 = (long)qt*128 + warp*16 + r;
    long base_lo = ((long)b*QLEN + q0)*DD + h*HDIM;
    long base_hi = base_lo + 8L*DD;
#pragma unroll
    for (int nj = 0; nj < 8; nj++) {
        int col = nj*8 + 2*c;
        float2 v0 = make_float2(tfround(o[nj][0]*inv_lo), tfround(o[nj][1]*inv_lo));
        float2 v1 = make_float2(tfround(o[nj][2]*inv_hi), tfround(o[nj][3]*inv_hi));
        *(float2*)(Out + base_lo + col) = v0;
        *(float2*)(Out + base_hi + col) = v1;
    }
}

// ---------------- host ----------------
extern "C" void kernel_launch(void* const* d_in, const int* in_sizes, int n_in,
                              void* d_out, int out_size)
{
    const float* hs  = (const float*)d_in[0];
    const float* ehs = (const float*)d_in[1];
    const float* wq  = (const float*)d_in[2];  const float* bq  = (const float*)d_in[3];
    const float* wk  = (const float*)d_in[4];  const float* bk  = (const float*)d_in[5];
    const float* wv  = (const float*)d_in[6];  const float* bv  = (const float*)d_in[7];
    const float* awq = (const float*)d_in[8];  const float* abq = (const float*)d_in[9];
    const float* awk = (const float*)d_in[10]; const float* abk = (const float*)d_in[11];
    const float* awv = (const float*)d_in[12]; const float* abv = (const float*)d_in[13];
    const float* wo  = (const float*)d_in[14]; const float* bo  = (const float*)d_in[15];
    const float* wao = (const float*)d_in[16]; const float* bao = (const float*)d_in[17];
    float* out = (float*)d_out;

    float *wqkv, *awqkv, *wot, *waot, *hst, *ehst, *bqkv, *abqkv;
    float *qkv, *eqkv, *mq, *sq, *mk, *sk, *Qb, *Kb, *Vtb, *ao;
    cudaGetSymbolAddress((void**)&wqkv,  g_wqkv);
    cudaGetSymbolAddress((void**)&awqkv, g_awqkv);
    cudaGetSymbolAddress((void**)&wot,   g_wot);
    cudaGetSymbolAddress((void**)&waot,  g_waot);
    cudaGetSymbolAddress((void**)&hst,   g_hst);
    cudaGetSymbolAddress((void**)&ehst,  g_ehst);
    cudaGetSymbolAddress((void**)&bqkv,  g_bqkv);
    cudaGetSymbolAddress((void**)&abqkv, g_abqkv);
    cudaGetSymbolAddress((void**)&qkv,   g_qkv);
    cudaGetSymbolAddress((void**)&eqkv,  g_eqkv);
    cudaGetSymbolAddress((void**)&mq,    g_mq);
    cudaGetSymbolAddress((void**)&sq,    g_sq);
    cudaGetSymbolAddress((void**)&mk,    g_mk);
    cudaGetSymbolAddress((void**)&sk,    g_sk);
    cudaGetSymbolAddress((void**)&Qb,    g_Q);
    cudaGetSymbolAddress((void**)&Kb,    g_K);
    cudaGetSymbolAddress((void**)&Vtb,   g_Vt);
    cudaGetSymbolAddress((void**)&ao,    g_ao);

    const int M1 = BB*SS;   // 4096
    const int M2 = BB*SE;   // 1024

    cudaFuncSetAttribute(gemm_tf32_kernel,
                         cudaFuncAttributeMaxDynamicSharedMemorySize, MMA_SMEM);
    cudaFuncSetAttribute(flash2_kernel,
                         cudaFuncAttributeMaxDynamicSharedMemorySize, F_SMEM2);

    // ---- conversions (tf32 pre-rounding + concat) ----
    {
        long nw = (long)DD*D3;
        concat3_tf32_kernel<<<(unsigned)((nw + 255)/256), 256>>>(wq, wk, wv, wqkv);
        concat3_tf32_kernel<<<(unsigned)((nw + 255)/256), 256>>>(awq, awk, awv, awqkv);
        int n4;
        n4 = DD*DD/4;       cvt4_kernel<<<(n4 + 255)/256, 256>>>((const float4*)wo,  (float4*)wot,  n4);
                            cvt4_kernel<<<(n4 + 255)/256, 256>>>((const float4*)wao, (float4*)waot, n4);
        n4 = BB*SS*DD/4;    cvt4_kernel<<<(n4 + 255)/256, 256>>>((const float4*)hs,  (float4*)hst,  n4);
        n4 = BB*SE*DD/4;    cvt4_kernel<<<(n4 + 255)/256, 256>>>((const float4*)ehs, (float4*)ehst, n4);
        bias_concat_kernel<<<(D3 + 255)/256, 256>>>(bq, bk, bv, bqkv);
        bias_concat_kernel<<<(D3 + 255)/256, 256>>>(abq, abk, abv, abqkv);
    }

    // ---- fused QKV projections ----
    gemm_tf32_kernel<<<dim3(D3/TBN, M1/TBM), 256, MMA_SMEM>>>(hst,  wqkv,  bqkv,  qkv,  M1, D3, DD, M1, 0, 0);
    gemm_tf32_kernel<<<dim3(D3/TBN, M2/TBM), 256, MMA_SMEM>>>(ehst, awqkv, abqkv, eqkv, M2, D3, DD, M2, 0, 0);

    // ---- AdaIN stats ----
    stats_kernel<<<dim3(DD/256, BB), 256>>>(qkv, mq, sq, 0);
    stats_kernel<<<dim3(DD/256, BB), 256>>>(qkv, mk, sk, DD);

    // ---- build permuted Q/K/V^T ----
    {
        long tq = (long)BB*HH*QLEN*HDIM;
        long tk = (long)BB*HH*KLEN*HDIM;
        build_q_kernel<<<(unsigned)((tq + 255)/256), 256>>>(qkv, eqkv, mq, sq, Qb);
        build_k_kernel<<<(unsigned)((tk + 255)/256), 256>>>(qkv, eqkv, mk, sk, Kb);
        build_v_kernel<<<(unsigned)((tk + 255)/256), 256>>>(qkv, eqkv, Vtb);
    }

    // ---- flash attention ----
    flash2_kernel<<<dim3(QLEN/128, HH, BB), 256, F_SMEM2>>>(Qb, Kb, Vtb, ao);

    // ---- output projections ----
    gemm_tf32_kernel<<<dim3(DD/TBN, M1/TBM), 256, MMA_SMEM>>>(ao, wot,  bo,  out,               M1, DD, DD, SS, QLEN, 0);
    gemm_tf32_kernel<<<dim3(DD/TBN, M2/TBM), 256, MMA_SMEM>>>(ao, waot, bao, out + (long)M1*DD, M2, DD, DD, SE, QLEN, SS);
}

// round 13
// speedup vs baseline: 3.1953x; 1.0159x over previous
#include <cuda_runtime.h>
#include <cuda_bf16.h>
#include <math.h>
#include <cstdint>

// Problem constants
#define BB 4
#define SS 1024
#define SE 256
#define DD 1536
#define HH 24
#define HDIM 64
#define QLEN (SS + SE)            // 1280
#define KLEN (2*SS + SE)          // 2304
#define D3 (3*DD)                 // 4608

// ---------------- scratch (device globals; no allocs allowed) ----------------
__device__ float g_wqkv[DD*D3];       // [wq|wk|wv] tf32-rounded
__device__ float g_awqkv[DD*D3];
__device__ float g_wot[DD*DD];
__device__ float g_waot[DD*DD];
__device__ float g_hst[BB*SS*DD];     // hs tf32-rounded
__device__ float g_ehst[BB*SE*DD];
__device__ float g_bqkv[D3];
__device__ float g_abqkv[D3];
__device__ float g_qkv[BB*SS*D3];     // fused QKV projection of hs
__device__ float g_eqkv[BB*SE*D3];
__device__ float g_mq[BB*DD];
__device__ float g_sq[BB*DD];
__device__ float g_mk[BB*DD];
__device__ float g_sk[BB*DD];
__device__ float g_Q[BB*HH*QLEN*HDIM];     // d-permuted, tf32
__device__ float g_K[BB*HH*KLEN*HDIM];     // d-permuted, tf32
__device__ float g_Vt[BB*HH*HDIM*KLEN];    // transposed + k-permuted, tf32
__device__ float g_ao[BB*QLEN*DD];         // flash out, tf32-rounded

// ---------------- common helpers ----------------
__device__ __forceinline__ uint32_t f2tf(float f) {
    uint32_t r;
    asm("cvt.rna.tf32.f32 %0, %1;" : "=r"(r) : "f"(f));
    return r;
}
__device__ __forceinline__ float tfround(float f) { return __uint_as_float(f2tf(f)); }

__device__ __forceinline__ void mma_tf32(float* c, const uint32_t* a,
                                         uint32_t b0, uint32_t b1) {
    asm volatile(
        "mma.sync.aligned.m16n8k8.row.col.f32.tf32.tf32.f32 "
        "{%0,%1,%2,%3}, {%4,%5,%6,%7}, {%8,%9}, {%0,%1,%2,%3};"
        : "+f"(c[0]), "+f"(c[1]), "+f"(c[2]), "+f"(c[3])
        : "r"(a[0]), "r"(a[1]), "r"(a[2]), "r"(a[3]), "r"(b0), "r"(b1));
}

__device__ __forceinline__ void cpasync16(uint32_t saddr, const void* gptr) {
    asm volatile("cp.async.ca.shared.global [%0], [%1], 16;"
                 :: "r"(saddr), "l"(gptr));
}

// position of element k (0..63) within a permuted 64-float row; row enters mod 16
__device__ __forceinline__ int permpos(int k, int row) {
    int c   = k & 3;
    int rem = 2*(k>>3) + ((k>>2)&1);        // 0..15
    int unit = (c + (rem & ~3) + row) & 15; // (rem&~3) == 4*t
    return unit*4 + (rem & 3);
}

// ---------------- conversion kernels ----------------
__global__ __launch_bounds__(256)
void cvt4_kernel(const float4* __restrict__ s, float4* __restrict__ d, int n4)
{
    int i = blockIdx.x*256 + threadIdx.x;
    if (i >= n4) return;
    float4 v = s[i];
    v.x = tfround(v.x); v.y = tfround(v.y); v.z = tfround(v.z); v.w = tfround(v.w);
    d[i] = v;
}

__global__ __launch_bounds__(256)
void concat3_tf32_kernel(const float* __restrict__ a, const float* __restrict__ b,
                         const float* __restrict__ c, float* __restrict__ dst)
{
    long i = (long)blockIdx.x*256 + threadIdx.x;     // over DD*D3
    if (i >= (long)DD*D3) return;
    int row = (int)(i / D3), col = (int)(i % D3);
    float v;
    if (col < DD)           v = a[(long)row*DD + col];
    else if (col < 2*DD)    v = b[(long)row*DD + col - DD];
    else                    v = c[(long)row*DD + col - 2*DD];
    dst[i] = tfround(v);
}

__global__ __launch_bounds__(256)
void bias_concat_kernel(const float* __restrict__ a, const float* __restrict__ b,
                        const float* __restrict__ c, float* __restrict__ dst)
{
    int i = blockIdx.x*256 + threadIdx.x;
    if (i >= D3) return;
    dst[i] = i < DD ? a[i] : (i < 2*DD ? b[i-DD] : c[i-2*DD]);
}

// ---------------- tf32 MMA GEMM (operands pre-rounded): C = A@W + bias ------
#define TBM 128
#define TBN 128
#define TBK 32
#define A_LD 36
#define B_LD 132
#define STAGE_A (TBM*A_LD)
#define STAGE_B (TBK*B_LD)
#define STAGE_SZ (STAGE_A + STAGE_B)
#define MMA_SMEM (2*STAGE_SZ*4)

__global__ __launch_bounds__(256)
void gemm_tf32_kernel(const float* __restrict__ A, const float* __restrict__ W,
                      const float* __restrict__ bias, float* __restrict__ C,
                      int M, int N, int K,
                      int rpb, int bstride, int roff)
{
    extern __shared__ float smf[];

    const int tid  = threadIdx.x;
    const int lane = tid & 31;
    const int warp = tid >> 5;
    const int wm = (warp & 3) * 32;
    const int wn = (warp >> 2) * 64;
    const int mbase = blockIdx.y * TBM;
    const int nbase = blockIdx.x * TBN;

    const float* aptr[4];
    uint32_t     sA[4];
    uint32_t     sB[4];
    const float* bptr[4];
#pragma unroll
    for (int i = 0; i < 4; i++) {
        int c = tid + 256*i;
        int row = c >> 3;
        int kc  = (c & 7) * 4;
        int grow = mbase + row;
        long prow = (long)(grow / rpb) * bstride + roff + (grow % rpb);
        aptr[i] = A + prow * K + kc;
        sA[i] = (uint32_t)__cvta_generic_to_shared(smf + row*A_LD + kc);

        int brow = c >> 5;
        int nc   = (c & 31) * 4;
        bptr[i] = W + (long)brow * N + nbase + nc;
        sB[i] = (uint32_t)__cvta_generic_to_shared(smf + STAGE_A + brow*B_LD + nc);
    }
    const uint32_t stage_bytes = STAGE_SZ * 4;

    float acc[2][8][4];
#pragma unroll
    for (int mi = 0; mi < 2; mi++)
#pragma unroll
        for (int nj = 0; nj < 8; nj++)
#pragma unroll
            for (int r = 0; r < 4; r++) acc[mi][nj][r] = 0.f;

    const int KT = K / TBK;

#pragma unroll
    for (int i = 0; i < 4; i++) {
        cpasync16(sA[i], aptr[i]);
        cpasync16(sB[i], bptr[i]);
    }
    asm volatile("cp.async.commit_group;");

    for (int t = 0; t < KT; t++) {
        if (t + 1 < KT) {
            int k0 = (t + 1) * TBK;
            uint32_t soff = ((t + 1) & 1) * stage_bytes;
#pragma unroll
            for (int i = 0; i < 4; i++) {
                cpasync16(sA[i] + soff, aptr[i] + k0);
                cpasync16(sB[i] + soff, bptr[i] + (long)k0 * N);
            }
        }
        asm volatile("cp.async.commit_group;");
        asm volatile("cp.async.wait_group %0;" :: "n"(1));
        __syncthreads();

        const float* As = smf + (t & 1) * STAGE_SZ;
        const float* Bs = As + STAGE_A;

#pragma unroll
        for (int kk = 0; kk < 4; kk++) {
            const int k = kk * 8;
            uint32_t af[2][4];
#pragma unroll
            for (int mi = 0; mi < 2; mi++) {
                int r = wm + mi*16 + (lane >> 2);
                int cc = k + (lane & 3);
                af[mi][0] = __float_as_uint(As[r*A_LD + cc]);
                af[mi][1] = __float_as_uint(As[(r+8)*A_LD + cc]);
                af[mi][2] = __float_as_uint(As[r*A_LD + cc + 4]);
                af[mi][3] = __float_as_uint(As[(r+8)*A_LD + cc + 4]);
            }
#pragma unroll
            for (int nj = 0; nj < 8; nj++) {
                int col = wn + nj*8 + (lane >> 2);
                uint32_t b0 = __float_as_uint(Bs[(k     + (lane & 3))*B_LD + col]);
                uint32_t b1 = __float_as_uint(Bs[(k + 4 + (lane & 3))*B_LD + col]);
                mma_tf32(acc[0][nj], af[0], b0, b1);
                mma_tf32(acc[1][nj], af[1], b0, b1);
            }
        }
        __syncthreads();
    }

#pragma unroll
    for (int mi = 0; mi < 2; mi++) {
        int row0 = mbase + wm + mi*16 + (lane >> 2);
        int row1 = row0 + 8;
#pragma unroll
        for (int nj = 0; nj < 8; nj++) {
            int col = nbase + wn + nj*8 + (lane & 3)*2;
            float b0 = bias[col], b1 = bias[col + 1];
            float2 v0 = make_float2(acc[mi][nj][0] + b0, acc[mi][nj][1] + b1);
            float2 v1 = make_float2(acc[mi][nj][2] + b0, acc[mi][nj][3] + b1);
            *(float2*)(C + (long)row0*N + col) = v0;
            *(float2*)(C + (long)row1*N + col) = v1;
        }
    }
}

// ---------------- AdaIN stats over g_qkv columns ----------------
__global__ __launch_bounds__(256)
void stats_kernel(const float* __restrict__ X, float* __restrict__ mean,
                  float* __restrict__ stdv, int coff)
{
    int d = blockIdx.x * 256 + threadIdx.x;
    int b = blockIdx.y;
    const float* p = X + (long)b*SS*D3 + coff + d;
    float s = 0.f, ss = 0.f;
    for (int i = 0; i < SS; i++) {
        float v = p[(long)i*D3];
        s += v; ss += v*v;
    }
    float mu = s * (1.f/1024.f);
    float var = (ss - 1024.f*mu*mu) * (1.f/1023.f);
    mean[b*DD + d] = mu;
    stdv[b*DD + d] = sqrtf(var + 1e-5f);
}

// ---------------- build Q (permuted, tf32) ----------------
__global__ __launch_bounds__(256)
void build_q_kernel(const float* __restrict__ qkv, const float* __restrict__ eqkv,
                    const float* __restrict__ mean, const float* __restrict__ stdv,
                    float* __restrict__ Outbuf)
{
    long idx = (long)blockIdx.x * 256 + threadIdx.x;
    if (idx >= (long)BB*HH*QLEN*HDIM) return;
    int hd = (int)(idx & 63);
    long t = idx >> 6;
    int p = (int)(t % QLEN); t /= QLEN;
    int h = (int)(t % HH);
    int b = (int)(t / HH);
    int d = h*HDIM + hd;
    float v;
    if (p < SS) {
        v = qkv[((long)b*SS + p)*D3 + d];
        if (b & 1) {
            int st = b - 1;
            v = (v - mean[b*DD+d]) / stdv[b*DD+d] * stdv[st*DD+d] + mean[st*DD+d];
        }
    } else {
        v = eqkv[((long)b*SE + (p - SS))*D3 + d];
    }
    Outbuf[(((long)b*HH + h)*QLEN + p)*64 + permpos(hd, p)] = tfround(v);
}

// ---------------- build K (permuted, tf32, style concat + adain) -------------
__global__ __launch_bounds__(256)
void build_k_kernel(const float* __restrict__ qkv, const float* __restrict__ eqkv,
                    const float* __restrict__ mean, const float* __restrict__ stdv,
                    float* __restrict__ Outbuf)
{
    long idx = (long)blockIdx.x * 256 + threadIdx.x;
    if (idx >= (long)BB*HH*KLEN*HDIM) return;
    int hd = (int)(idx & 63);
    long t = idx >> 6;
    int p = (int)(t % KLEN); t /= KLEN;
    int h = (int)(t % HH);
    int b = (int)(t / HH);
    int d = h*HDIM + hd;
    float v;
    if (p < SS) {
        v = qkv[((long)b*SS + p)*D3 + DD + d];
        if (b & 1) {
            int st = b - 1;
            v = (v - mean[b*DD+d]) / stdv[b*DD+d] * stdv[st*DD+d] + mean[st*DD+d];
        }
    } else if (p < 2*SS) {
        int st = (b >> 1) << 1;
        v = qkv[((long)st*SS + (p - SS))*D3 + DD + d];
    } else {
        v = eqkv[((long)b*SE + (p - 2*SS))*D3 + DD + d];
    }
    Outbuf[(((long)b*HH + h)*KLEN + p)*64 + permpos(hd, p)] = tfround(v);
}

// ---------------- build V^T: smem-tiled transpose (coalesced both sides) ----
// Block: one (b, h, 64-p slab). Read p x hd with hd fastest (coalesced),
// store permuted into smem (stride 65 -> conflict-free: bank step 5 mod 32),
// write V^T rows as contiguous 64B runs.
__global__ __launch_bounds__(256)
void build_vt_kernel(const float* __restrict__ qkv, const float* __restrict__ eqkv,
                     float* __restrict__ Outbuf)
{
    __shared__ float ts[64*65];

    const int pblk = blockIdx.x * 64;
    const int h = blockIdx.y;
    const int b = blockIdx.z;
    const int tid = threadIdx.x;
    const int hd = tid & 63;
    const int d = h*HDIM + hd;

#pragma unroll
    for (int it = 0; it < 16; it++) {
        int pl = it*4 + (tid >> 6);           // 0..63
        int p = pblk + pl;
        float v;
        if (p < SS) {
            v = qkv[((long)b*SS + p)*D3 + 2*DD + d];
        } else if (p < 2*SS) {
            int st = (b >> 1) << 1;
            v = qkv[((long)st*SS + (p - SS))*D3 + 2*DD + d];
        } else {
            v = eqkv[((long)b*SE + (p - 2*SS))*D3 + 2*DD + d];
        }
        ts[hd*65 + permpos(pl, hd)] = tfround(v);
    }
    __syncthreads();

    // write: 64 hd-rows x 16 float4; thread -> (hd = tid>>2, q = tid&3),
    // unit = 4j + q so each warp stores 8 x 64B contiguous runs
    const int whd = tid >> 2;
    const int q = tid & 3;
    float* obase = Outbuf + (((long)b*HH + h)*64 + whd)*(long)KLEN + pblk;
    const float* srow = ts + whd*65;
#pragma unroll
    for (int j = 0; j < 4; j++) {
        int unit = j*4 + q;
        float4 v;
        v.x = srow[unit*4 + 0];
        v.y = srow[unit*4 + 1];
        v.z = srow[unit*4 + 2];
        v.w = srow[unit*4 + 3];
        *(float4*)(obase + unit*4) = v;
    }
}

// ---------------- Flash attention: vectorized tf32 MMA ----------------------
#define FKLD 76
#define F_QS  (128*FKLD)          // 9728 floats (Q tile, then P staging)
#define F_KST (64*FKLD)           // 4864 floats per stage
#define F_SMEM2 ((F_QS + 4*F_KST)*4)   // 116,736 bytes

__global__ __launch_bounds__(256)
void flash2_kernel(const float* __restrict__ Qg, const float* __restrict__ Kg,
                   const float* __restrict__ Vg, float* __restrict__ Out)
{
    extern __shared__ float sm[];
    float* Qs  = sm;                 // Q tile then P staging
    float* Kst = sm + F_QS;
    float* Vst = Kst + 2*F_KST;

    const int qt = blockIdx.x, h = blockIdx.y, b = blockIdx.z;
    const int tid = threadIdx.x, lane = tid & 31, warp = tid >> 5;
    const int r = lane >> 2, c = lane & 3;
    const int mrow = warp*16 + r;

    const float* Qbase = Qg + (((long)b*HH + h)*QLEN + qt*128) * 64;
    const float* Kbase = Kg + ((long)b*HH + h) * KLEN * 64;
    const float* Vbase = Vg + ((long)b*HH + h) * HDIM * (long)KLEN;

    // ---- Q tile: 2048 16B chunks ----
#pragma unroll
    for (int i = 0; i < 8; i++) {
        int g = tid + 256*i;
        int row = g >> 4, u = g & 15;
        cpasync16((uint32_t)__cvta_generic_to_shared(Qs + row*FKLD + u*4),
                  Qbase + row*64 + u*4);
    }
    asm volatile("cp.async.commit_group;");

    // ---- KV tile 0 ----
    const float* kp[4]; const float* vp[4];
    uint32_t sK[4], sV[4];
#pragma unroll
    for (int i = 0; i < 4; i++) {
        int g = tid + 256*i;
        int row = g >> 4, u = g & 15;
        kp[i] = Kbase + row*64 + u*4;
        vp[i] = Vbase + (long)row*KLEN + u*4;
        sK[i] = (uint32_t)__cvta_generic_to_shared(Kst + row*FKLD + u*4);
        sV[i] = (uint32_t)__cvta_generic_to_shared(Vst + row*FKLD + u*4);
        cpasync16(sK[i], kp[i]);
        cpasync16(sV[i], vp[i]);
    }
    asm volatile("cp.async.commit_group;");
    asm volatile("cp.async.wait_group 1;");   // Q arrived
    __syncthreads();

    // ---- extract Q A-fragments (already tf32 bit patterns) ----
    uint32_t qf[8][4];
#pragma unroll
    for (int t = 0; t < 4; t++) {
        int u0 = (c + 4*t + mrow) & 15;
        int u1 = (c + 4*t + mrow + 8) & 15;
        float4 f0 = *(const float4*)(Qs + mrow*FKLD + u0*4);
        float4 f1 = *(const float4*)(Qs + (mrow+8)*FKLD + u1*4);
        qf[2*t][0]   = __float_as_uint(f0.x); qf[2*t][1]   = __float_as_uint(f1.x);
        qf[2*t][2]   = __float_as_uint(f0.y); qf[2*t][3]   = __float_as_uint(f1.y);
        qf[2*t+1][0] = __float_as_uint(f0.z); qf[2*t+1][1] = __float_as_uint(f1.z);
        qf[2*t+1][2] = __float_as_uint(f0.w); qf[2*t+1][3] = __float_as_uint(f1.w);
    }
    __syncthreads();   // all warps done reading Q; Qs becomes P staging

    float m_lo = -1e30f, m_hi = -1e30f, l_lo = 0.f, l_hi = 0.f;
    float o[8][4];
#pragma unroll
    for (int nj = 0; nj < 8; nj++)
#pragma unroll
        for (int i = 0; i < 4; i++) o[nj][i] = 0.f;

    const float scale = 0.125f;
    const int NT = KLEN / 64;     // 36

    for (int tt = 0; tt < NT; tt++) {
        if (tt + 1 < NT) {
            uint32_t so = ((tt + 1) & 1) * (F_KST * 4);
            long kgo = (long)(tt + 1) * 4096;
            long vgo = (long)(tt + 1) * 64;
#pragma unroll
            for (int i = 0; i < 4; i++) {
                cpasync16(sK[i] + so, kp[i] + kgo);
                cpasync16(sV[i] + so, vp[i] + vgo);
            }
        }
        asm volatile("cp.async.commit_group;");
        asm volatile("cp.async.wait_group %0;" :: "n"(1));
        __syncthreads();

        const float* K0 = Kst + (tt & 1) * F_KST;
        const float* V0 = Vst + (tt & 1) * F_KST;

        // ---- S = Q K^T ----
        float s[8][4];
#pragma unroll
        for (int nj = 0; nj < 8; nj++)
#pragma unroll
            for (int i = 0; i < 4; i++) s[nj][i] = 0.f;

#pragma unroll
        for (int t = 0; t < 4; t++) {
#pragma unroll
            for (int nj = 0; nj < 8; nj++) {
                int row = nj*8 + r;
                int u = (c + 4*t + row) & 15;
                float4 f = *(const float4*)(K0 + row*FKLD + u*4);
                mma_tf32(s[nj], qf[2*t],   __float_as_uint(f.x), __float_as_uint(f.y));
                mma_tf32(s[nj], qf[2*t+1], __float_as_uint(f.z), __float_as_uint(f.w));
            }
        }

        // ---- online softmax ----
        float tmax_lo = -1e30f, tmax_hi = -1e30f;
#pragma unroll
        for (int nj = 0; nj < 8; nj++) {
            s[nj][0] *= scale; s[nj][1] *= scale;
            s[nj][2] *= scale; s[nj][3] *= scale;
            tmax_lo = fmaxf(tmax_lo, fmaxf(s[nj][0], s[nj][1]));
            tmax_hi = fmaxf(tmax_hi, fmaxf(s[nj][2], s[nj][3]));
        }
        tmax_lo = fmaxf(tmax_lo, __shfl_xor_sync(0xffffffffu, tmax_lo, 1));
        tmax_lo = fmaxf(tmax_lo, __shfl_xor_sync(0xffffffffu, tmax_lo, 2));
        tmax_hi = fmaxf(tmax_hi, __shfl_xor_sync(0xffffffffu, tmax_hi, 1));
        tmax_hi = fmaxf(tmax_hi, __shfl_xor_sync(0xffffffffu, tmax_hi, 2));

        float mn_lo = fmaxf(m_lo, tmax_lo);
        float mn_hi = fmaxf(m_hi, tmax_hi);
        float corr_lo = __expf(m_lo - mn_lo);
        float corr_hi = __expf(m_hi - mn_hi);

        float ps_lo = 0.f, ps_hi = 0.f;
#pragma unroll
        for (int nj = 0; nj < 8; nj++) {
            float p0 = __expf(s[nj][0] - mn_lo);
            float p1 = __expf(s[nj][1] - mn_lo);
            float p2 = __expf(s[nj][2] - mn_hi);
            float p3 = __expf(s[nj][3] - mn_hi);
            ps_lo += p0 + p1;
            ps_hi += p2 + p3;
            int col = nj*8 + 2*c;
            float2 v0; v0.x = __uint_as_float(f2tf(p0)); v0.y = __uint_as_float(f2tf(p1));
            float2 v1; v1.x = __uint_as_float(f2tf(p2)); v1.y = __uint_as_float(f2tf(p3));
            *(float2*)(Qs + mrow*FKLD + col) = v0;
            *(float2*)(Qs + (mrow+8)*FKLD + col) = v1;
        }
        ps_lo += __shfl_xor_sync(0xffffffffu, ps_lo, 1);
        ps_lo += __shfl_xor_sync(0xffffffffu, ps_lo, 2);
        ps_hi += __shfl_xor_sync(0xffffffffu, ps_hi, 1);
        ps_hi += __shfl_xor_sync(0xffffffffu, ps_hi, 2);

        l_lo = l_lo*corr_lo + ps_lo;  m_lo = mn_lo;
        l_hi = l_hi*corr_hi + ps_hi;  m_hi = mn_hi;
#pragma unroll
        for (int nj = 0; nj < 8; nj++) {
            o[nj][0] *= corr_lo; o[nj][1] *= corr_lo;
            o[nj][2] *= corr_hi; o[nj][3] *= corr_hi;
        }
        __syncwarp();

        // ---- O += P V ----
#pragma unroll
        for (int t = 0; t < 4; t++) {
            int k0 = 16*t + c;
            int k1 = k0 + 8;
            uint32_t a0[4], a1[4];
            a0[0] = __float_as_uint(Qs[mrow*FKLD + k0]);
            a0[1] = __float_as_uint(Qs[(mrow+8)*FKLD + k0]);
            a0[2] = __float_as_uint(Qs[mrow*FKLD + k0 + 4]);
            a0[3] = __float_as_uint(Qs[(mrow+8)*FKLD + k0 + 4]);
            a1[0] = __float_as_uint(Qs[mrow*FKLD + k1]);
            a1[1] = __float_as_uint(Qs[(mrow+8)*FKLD + k1]);
            a1[2] = __float_as_uint(Qs[mrow*FKLD + k1 + 4]);
            a1[3] = __float_as_uint(Qs[(mrow+8)*FKLD + k1 + 4]);
#pragma unroll
            for (int nj = 0; nj < 8; nj++) {
                int row = nj*8 + r;
                int u = (c + 4*t + row) & 15;
                float4 f = *(const float4*)(V0 + row*FKLD + u*4);
                mma_tf32(o[nj], a0, __float_as_uint(f.x), __float_as_uint(f.y));
                mma_tf32(o[nj], a1, __float_as_uint(f.z), __float_as_uint(f.w));
            }
        }
        __syncwarp();
        __syncthreads();   // P staging + stage (tt&1) free for reuse
    }

    // ---- normalize + write out [B, QLEN, D], tf32-rounded for out-proj ----
    float inv_lo = 1.f / l_lo;
    float inv_hi = 1.f / l_hi;
    long q0 = (long)qt*128 + warp*16 + r;
    long base_lo = ((long)b*QLEN + q0)*DD + h*HDIM;
    long base_hi = base_lo + 8L*DD;
#pragma unroll
    for (int nj = 0; nj < 8; nj++) {
        int col = nj*8 + 2*c;
        float2 v0 = make_float2(tfround(o[nj][0]*inv_lo), tfround(o[nj][1]*inv_lo));
        float2 v1 = make_float2(tfround(o[nj][2]*inv_hi), tfround(o[nj][3]*inv_hi));
        *(float2*)(Out + base_lo + col) = v0;
        *(float2*)(Out + base_hi + col) = v1;
    }
}

// ---------------- host ----------------
extern "C" void kernel_launch(void* const* d_in, const int* in_sizes, int n_in,
                              void* d_out, int out_size)
{
    const float* hs  = (const float*)d_in[0];
    const float* ehs = (const float*)d_in[1];
    const float* wq  = (const float*)d_in[2];  const float* bq  = (const float*)d_in[3];
    const float* wk  = (const float*)d_in[4];  const float* bk  = (const float*)d_in[5];
    const float* wv  = (const float*)d_in[6];  const float* bv  = (const float*)d_in[7];
    const float* awq = (const float*)d_in[8];  const float* abq = (const float*)d_in[9];
    const float* awk = (const float*)d_in[10]; const float* abk = (const float*)d_in[11];
    const float* awv = (const float*)d_in[12]; const float* abv = (const float*)d_in[13];
    const float* wo  = (const float*)d_in[14]; const float* bo  = (const float*)d_in[15];
    const float* wao = (const float*)d_in[16]; const float* bao = (const float*)d_in[17];
    float* out = (float*)d_out;

    float *wqkv, *awqkv, *wot, *waot, *hst, *ehst, *bqkv, *abqkv;
    float *qkv, *eqkv, *mq, *sq, *mk, *sk, *Qb, *Kb, *Vtb, *ao;
    cudaGetSymbolAddress((void**)&wqkv,  g_wqkv);
    cudaGetSymbolAddress((void**)&awqkv, g_awqkv);
    cudaGetSymbolAddress((void**)&wot,   g_wot);
    cudaGetSymbolAddress((void**)&waot,  g_waot);
    cudaGetSymbolAddress((void**)&hst,   g_hst);
    cudaGetSymbolAddress((void**)&ehst,  g_ehst);
    cudaGetSymbolAddress((void**)&bqkv,  g_bqkv);
    cudaGetSymbolAddress((void**)&abqkv, g_abqkv);
    cudaGetSymbolAddress((void**)&qkv,   g_qkv);
    cudaGetSymbolAddress((void**)&eqkv,  g_eqkv);
    cudaGetSymbolAddress((void**)&mq,    g_mq);
    cudaGetSymbolAddress((void**)&sq,    g_sq);
    cudaGetSymbolAddress((void**)&mk,    g_mk);
    cudaGetSymbolAddress((void**)&sk,    g_sk);
    cudaGetSymbolAddress((void**)&Qb,    g_Q);
    cudaGetSymbolAddress((void**)&Kb,    g_K);
    cudaGetSymbolAddress((void**)&Vtb,   g_Vt);
    cudaGetSymbolAddress((void**)&ao,    g_ao);

    const int M1 = BB*SS;   // 4096
    const int M2 = BB*SE;   // 1024

    cudaFuncSetAttribute(gemm_tf32_kernel,
                         cudaFuncAttributeMaxDynamicSharedMemorySize, MMA_SMEM);
    cudaFuncSetAttribute(flash2_kernel,
                         cudaFuncAttributeMaxDynamicSharedMemorySize, F_SMEM2);

    // ---- conversions (tf32 pre-rounding + concat) ----
    {
        long nw = (long)DD*D3;
        concat3_tf32_kernel<<<(unsigned)((nw + 255)/256), 256>>>(wq, wk, wv, wqkv);
        concat3_tf32_kernel<<<(unsigned)((nw + 255)/256), 256>>>(awq, awk, awv, awqkv);
        int n4;
        n4 = DD*DD/4;       cvt4_kernel<<<(n4 + 255)/256, 256>>>((const float4*)wo,  (float4*)wot,  n4);
                            cvt4_kernel<<<(n4 + 255)/256, 256>>>((const float4*)wao, (float4*)waot, n4);
        n4 = BB*SS*DD/4;    cvt4_kernel<<<(n4 + 255)/256, 256>>>((const float4*)hs,  (float4*)hst,  n4);
        n4 = BB*SE*DD/4;    cvt4_kernel<<<(n4 + 255)/256, 256>>>((const float4*)ehs, (float4*)ehst, n4);
        bias_concat_kernel<<<(D3 + 255)/256, 256>>>(bq, bk, bv, bqkv);
        bias_concat_kernel<<<(D3 + 255)/256, 256>>>(abq, abk, abv, abqkv);
    }

    // ---- fused QKV projections ----
    gemm_tf32_kernel<<<dim3(D3/TBN, M1/TBM), 256, MMA_SMEM>>>(hst,  wqkv,  bqkv,  qkv,  M1, D3, DD, M1, 0, 0);
    gemm_tf32_kernel<<<dim3(D3/TBN, M2/TBM), 256, MMA_SMEM>>>(ehst, awqkv, abqkv, eqkv, M2, D3, DD, M2, 0, 0);

    // ---- AdaIN stats ----
    stats_kernel<<<dim3(DD/256, BB), 256>>>(qkv, mq, sq, 0);
    stats_kernel<<<dim3(DD/256, BB), 256>>>(qkv, mk, sk, DD);

    // ---- build permuted Q/K/V^T ----
    {
        long tq = (long)BB*HH*QLEN*HDIM;
        long tk = (long)BB*HH*KLEN*HDIM;
        build_q_kernel<<<(unsigned)((tq + 255)/256), 256>>>(qkv, eqkv, mq, sq, Qb);
        build_k_kernel<<<(unsigned)((tk + 255)/256), 256>>>(qkv, eqkv, mk, sk, Kb);
        build_vt_kernel<<<dim3(KLEN/64, HH, BB), 256>>>(qkv, eqkv, Vtb);
    }

    // ---- flash attention ----
    flash2_kernel<<<dim3(QLEN/128, HH, BB), 256, F_SMEM2>>>(Qb, Kb, Vtb, ao);

    // ---- output projections ----
    gemm_tf32_kernel<<<dim3(DD/TBN, M1/TBM), 256, MMA_SMEM>>>(ao, wot,  bo,  out,               M1, DD, DD, SS, QLEN, 0);
    gemm_tf32_kernel<<<dim3(DD/TBN, M2/TBM), 256, MMA_SMEM>>>(ao, waot, bao, out + (long)M1*DD, M2, DD, DD, SE, QLEN, SS);
}

// round 15
// speedup vs baseline: 3.2967x; 1.0317x over previous
#include <cuda_runtime.h>
#include <cuda_bf16.h>
#include <math.h>
#include <cstdint>

// Problem constants
#define BB 4
#define SS 1024
#define SE 256
#define DD 1536
#define HH 24
#define HDIM 64
#define QLEN (SS + SE)            // 1280
#define KLEN (2*SS + SE)          // 2304
#define D3 (3*DD)                 // 4608

// ---------------- scratch (device globals; no allocs allowed) ----------------
__device__ float g_wqkv[DD*D3];       // [wq|wk|wv] tf32-rounded
__device__ float g_awqkv[DD*D3];
__device__ float g_wot[DD*DD];
__device__ float g_waot[DD*DD];
__device__ float g_hst[BB*SS*DD];     // hs tf32-rounded
__device__ float g_ehst[BB*SE*DD];
__device__ float g_bqkv[D3];
__device__ float g_abqkv[D3];
__device__ float g_qkv[BB*SS*D3];     // fused QKV projection of hs
__device__ float g_eqkv[BB*SE*D3];
__device__ float g_mq[BB*DD];
__device__ float g_sq[BB*DD];
__device__ float g_mk[BB*DD];
__device__ float g_sk[BB*DD];
__device__ float g_Q[BB*HH*QLEN*HDIM];     // d-permuted, tf32
__device__ float g_K[BB*HH*KLEN*HDIM];     // d-permuted, tf32
__device__ float g_Vt[BB*HH*HDIM*KLEN];    // transposed + k-permuted, tf32
__device__ float g_ao[BB*QLEN*DD];         // flash out, tf32-rounded

// ---------------- common helpers ----------------
__device__ __forceinline__ uint32_t f2tf(float f) {
    uint32_t r;
    asm("cvt.rna.tf32.f32 %0, %1;" : "=r"(r) : "f"(f));
    return r;
}
__device__ __forceinline__ float tfround(float f) { return __uint_as_float(f2tf(f)); }

__device__ __forceinline__ void mma_tf32(float* c, const uint32_t* a,
                                         uint32_t b0, uint32_t b1) {
    asm volatile(
        "mma.sync.aligned.m16n8k8.row.col.f32.tf32.tf32.f32 "
        "{%0,%1,%2,%3}, {%4,%5,%6,%7}, {%8,%9}, {%0,%1,%2,%3};"
        : "+f"(c[0]), "+f"(c[1]), "+f"(c[2]), "+f"(c[3])
        : "r"(a[0]), "r"(a[1]), "r"(a[2]), "r"(a[3]), "r"(b0), "r"(b1));
}

__device__ __forceinline__ void cpasync16(uint32_t saddr, const void* gptr) {
    asm volatile("cp.async.ca.shared.global [%0], [%1], 16;"
                 :: "r"(saddr), "l"(gptr));
}

// position of element k (0..63) within a permuted 64-float row; row enters mod 16
__device__ __forceinline__ int permpos(int k, int row) {
    int c   = k & 3;
    int rem = 2*(k>>3) + ((k>>2)&1);        // 0..15
    int unit = (c + (rem & ~3) + row) & 15; // (rem&~3) == 4*t
    return unit*4 + (rem & 3);
}

// ---------------- conversion kernels ----------------
__global__ __launch_bounds__(256)
void cvt4_kernel(const float4* __restrict__ s, float4* __restrict__ d, int n4)
{
    int i = blockIdx.x*256 + threadIdx.x;
    if (i >= n4) return;
    float4 v = s[i];
    v.x = tfround(v.x); v.y = tfround(v.y); v.z = tfround(v.z); v.w = tfround(v.w);
    d[i] = v;
}

__global__ __launch_bounds__(256)
void concat3_tf32_kernel(const float* __restrict__ a, const float* __restrict__ b,
                         const float* __restrict__ c, float* __restrict__ dst)
{
    long i = (long)blockIdx.x*256 + threadIdx.x;     // over DD*D3
    if (i >= (long)DD*D3) return;
    int row = (int)(i / D3), col = (int)(i % D3);
    float v;
    if (col < DD)           v = a[(long)row*DD + col];
    else if (col < 2*DD)    v = b[(long)row*DD + col - DD];
    else                    v = c[(long)row*DD + col - 2*DD];
    dst[i] = tfround(v);
}

__global__ __launch_bounds__(256)
void bias_concat_kernel(const float* __restrict__ a, const float* __restrict__ b,
                        const float* __restrict__ c, float* __restrict__ dst)
{
    int i = blockIdx.x*256 + threadIdx.x;
    if (i >= D3) return;
    dst[i] = i < DD ? a[i] : (i < 2*DD ? b[i-DD] : c[i-2*DD]);
}

// ---------------- tf32 MMA GEMM (operands pre-rounded): C = A@W + bias ------
#define TBM 128
#define TBN 128
#define TBK 32
#define A_LD 36
#define B_LD 132
#define STAGE_A (TBM*A_LD)
#define STAGE_B (TBK*B_LD)
#define STAGE_SZ (STAGE_A + STAGE_B)
#define MMA_SMEM (2*STAGE_SZ*4)

__global__ __launch_bounds__(256)
void gemm_tf32_kernel(const float* __restrict__ A, const float* __restrict__ W,
                      const float* __restrict__ bias, float* __restrict__ C,
                      int M, int N, int K,
                      int rpb, int bstride, int roff)
{
    extern __shared__ float smf[];

    const int tid  = threadIdx.x;
    const int lane = tid & 31;
    const int warp = tid >> 5;
    const int wm = (warp & 3) * 32;
    const int wn = (warp >> 2) * 64;
    const int mbase = blockIdx.y * TBM;
    const int nbase = blockIdx.x * TBN;

    const float* aptr[4];
    uint32_t     sA[4];
    uint32_t     sB[4];
    const float* bptr[4];
#pragma unroll
    for (int i = 0; i < 4; i++) {
        int c = tid + 256*i;
        int row = c >> 3;
        int kc  = (c & 7) * 4;
        int grow = mbase + row;
        long prow = (long)(grow / rpb) * bstride + roff + (grow % rpb);
        aptr[i] = A + prow * K + kc;
        sA[i] = (uint32_t)__cvta_generic_to_shared(smf + row*A_LD + kc);

        int brow = c >> 5;
        int nc   = (c & 31) * 4;
        bptr[i] = W + (long)brow * N + nbase + nc;
        sB[i] = (uint32_t)__cvta_generic_to_shared(smf + STAGE_A + brow*B_LD + nc);
    }
    const uint32_t stage_bytes = STAGE_SZ * 4;

    float acc[2][8][4];
#pragma unroll
    for (int mi = 0; mi < 2; mi++)
#pragma unroll
        for (int nj = 0; nj < 8; nj++)
#pragma unroll
            for (int r = 0; r < 4; r++) acc[mi][nj][r] = 0.f;

    const int KT = K / TBK;

#pragma unroll
    for (int i = 0; i < 4; i++) {
        cpasync16(sA[i], aptr[i]);
        cpasync16(sB[i], bptr[i]);
    }
    asm volatile("cp.async.commit_group;");

    for (int t = 0; t < KT; t++) {
        if (t + 1 < KT) {
            int k0 = (t + 1) * TBK;
            uint32_t soff = ((t + 1) & 1) * stage_bytes;
#pragma unroll
            for (int i = 0; i < 4; i++) {
                cpasync16(sA[i] + soff, aptr[i] + k0);
                cpasync16(sB[i] + soff, bptr[i] + (long)k0 * N);
            }
        }
        asm volatile("cp.async.commit_group;");
        asm volatile("cp.async.wait_group %0;" :: "n"(1));
        __syncthreads();

        const float* As = smf + (t & 1) * STAGE_SZ;
        const float* Bs = As + STAGE_A;

#pragma unroll
        for (int kk = 0; kk < 4; kk++) {
            const int k = kk * 8;
            uint32_t af[2][4];
#pragma unroll
            for (int mi = 0; mi < 2; mi++) {
                int r = wm + mi*16 + (lane >> 2);
                int cc = k + (lane & 3);
                af[mi][0] = __float_as_uint(As[r*A_LD + cc]);
                af[mi][1] = __float_as_uint(As[(r+8)*A_LD + cc]);
                af[mi][2] = __float_as_uint(As[r*A_LD + cc + 4]);
                af[mi][3] = __float_as_uint(As[(r+8)*A_LD + cc + 4]);
            }
#pragma unroll
            for (int nj = 0; nj < 8; nj++) {
                int col = wn + nj*8 + (lane >> 2);
                uint32_t b0 = __float_as_uint(Bs[(k     + (lane & 3))*B_LD + col]);
                uint32_t b1 = __float_as_uint(Bs[(k + 4 + (lane & 3))*B_LD + col]);
                mma_tf32(acc[0][nj], af[0], b0, b1);
                mma_tf32(acc[1][nj], af[1], b0, b1);
            }
        }
        __syncthreads();
    }

#pragma unroll
    for (int mi = 0; mi < 2; mi++) {
        int row0 = mbase + wm + mi*16 + (lane >> 2);
        int row1 = row0 + 8;
#pragma unroll
        for (int nj = 0; nj < 8; nj++) {
            int col = nbase + wn + nj*8 + (lane & 3)*2;
            float b0 = bias[col], b1 = bias[col + 1];
            float2 v0 = make_float2(acc[mi][nj][0] + b0, acc[mi][nj][1] + b1);
            float2 v1 = make_float2(acc[mi][nj][2] + b0, acc[mi][nj][3] + b1);
            *(float2*)(C + (long)row0*N + col) = v0;
            *(float2*)(C + (long)row1*N + col) = v1;
        }
    }
}

// ---------------- AdaIN stats over g_qkv columns ----------------
__global__ __launch_bounds__(256)
void stats_kernel(const float* __restrict__ X, float* __restrict__ mean,
                  float* __restrict__ stdv, int coff)
{
    int d = blockIdx.x * 256 + threadIdx.x;
    int b = blockIdx.y;
    const float* p = X + (long)b*SS*D3 + coff + d;
    float s = 0.f, ss = 0.f;
    for (int i = 0; i < SS; i++) {
        float v = p[(long)i*D3];
        s += v; ss += v*v;
    }
    float mu = s * (1.f/1024.f);
    float var = (ss - 1024.f*mu*mu) * (1.f/1023.f);
    mean[b*DD + d] = mu;
    stdv[b*DD + d] = sqrtf(var + 1e-5f);
}

// ---------------- build Q (permuted, tf32) ----------------
__global__ __launch_bounds__(256)
void build_q_kernel(const float* __restrict__ qkv, const float* __restrict__ eqkv,
                    const float* __restrict__ mean, const float* __restrict__ stdv,
                    float* __restrict__ Outbuf)
{
    long idx = (long)blockIdx.x * 256 + threadIdx.x;
    if (idx >= (long)BB*HH*QLEN*HDIM) return;
    int hd = (int)(idx & 63);
    long t = idx >> 6;
    int p = (int)(t % QLEN); t /= QLEN;
    int h = (int)(t % HH);
    int b = (int)(t / HH);
    int d = h*HDIM + hd;
    float v;
    if (p < SS) {
        v = qkv[((long)b*SS + p)*D3 + d];
        if (b & 1) {
            int st = b - 1;
            v = (v - mean[b*DD+d]) / stdv[b*DD+d] * stdv[st*DD+d] + mean[st*DD+d];
        }
    } else {
        v = eqkv[((long)b*SE + (p - SS))*D3 + d];
    }
    Outbuf[(((long)b*HH + h)*QLEN + p)*64 + permpos(hd, p)] = tfround(v);
}

// ---------------- build K (permuted, tf32, style concat + adain) -------------
__global__ __launch_bounds__(256)
void build_k_kernel(const float* __restrict__ qkv, const float* __restrict__ eqkv,
                    const float* __restrict__ mean, const float* __restrict__ stdv,
                    float* __restrict__ Outbuf)
{
    long idx = (long)blockIdx.x * 256 + threadIdx.x;
    if (idx >= (long)BB*HH*KLEN*HDIM) return;
    int hd = (int)(idx & 63);
    long t = idx >> 6;
    int p = (int)(t % KLEN); t /= KLEN;
    int h = (int)(t % HH);
    int b = (int)(t / HH);
    int d = h*HDIM + hd;
    float v;
    if (p < SS) {
        v = qkv[((long)b*SS + p)*D3 + DD + d];
        if (b & 1) {
            int st = b - 1;
            v = (v - mean[b*DD+d]) / stdv[b*DD+d] * stdv[st*DD+d] + mean[st*DD+d];
        }
    } else if (p < 2*SS) {
        int st = (b >> 1) << 1;
        v = qkv[((long)st*SS + (p - SS))*D3 + DD + d];
    } else {
        v = eqkv[((long)b*SE + (p - 2*SS))*D3 + DD + d];
    }
    Outbuf[(((long)b*HH + h)*KLEN + p)*64 + permpos(hd, p)] = tfround(v);
}

// ---------------- build V^T: smem-tiled transpose (coalesced both sides) ----
__global__ __launch_bounds__(256)
void build_vt_kernel(const float* __restrict__ qkv, const float* __restrict__ eqkv,
                     float* __restrict__ Outbuf)
{
    __shared__ float ts[64*65];

    const int pblk = blockIdx.x * 64;
    const int h = blockIdx.y;
    const int b = blockIdx.z;
    const int tid = threadIdx.x;
    const int hd = tid & 63;
    const int d = h*HDIM + hd;

#pragma unroll
    for (int it = 0; it < 16; it++) {
        int pl = it*4 + (tid >> 6);           // 0..63
        int p = pblk + pl;
        float v;
        if (p < SS) {
            v = qkv[((long)b*SS + p)*D3 + 2*DD + d];
        } else if (p < 2*SS) {
            int st = (b >> 1) << 1;
            v = qkv[((long)st*SS + (p - SS))*D3 + 2*DD + d];
        } else {
            v = eqkv[((long)b*SE + (p - 2*SS))*D3 + 2*DD + d];
        }
        ts[hd*65 + permpos(pl, hd)] = tfround(v);
    }
    __syncthreads();

    const int whd = tid >> 2;
    const int q = tid & 3;
    float* obase = Outbuf + (((long)b*HH + h)*64 + whd)*(long)KLEN + pblk;
    const float* srow = ts + whd*65;
#pragma unroll
    for (int j = 0; j < 4; j++) {
        int unit = j*4 + q;
        float4 v;
        v.x = srow[unit*4 + 0];
        v.y = srow[unit*4 + 1];
        v.z = srow[unit*4 + 2];
        v.w = srow[unit*4 + 3];
        *(float4*)(obase + unit*4) = v;
    }
}

// ---------------- Flash attention v3: 128 threads, BQ=64, occ 2 -------------
#define FP_LD 68
#define FK_LD 76
#define F_P (64*FP_LD)            // 4352 floats (Q tile, then P staging)
#define F_K (64*FK_LD)            // 4864 floats per stage
#define F_SMEM3 ((F_P + 4*F_K)*4) // 95,232 bytes -> 2 CTAs/SM

__global__ __launch_bounds__(128)
void flash3_kernel(const float* __restrict__ Qg, const float* __restrict__ Kg,
                   const float* __restrict__ Vg, float* __restrict__ Out)
{
    extern __shared__ float sm[];
    float* Ps  = sm;                 // Q tile then P staging (ld 68)
    float* Kst = sm + F_P;           // 2 stages (ld 76)
    float* Vst = Kst + 2*F_K;        // 2 stages (ld 76)

    const int qt = blockIdx.x, h = blockIdx.y, b = blockIdx.z;
    const int tid = threadIdx.x, lane = tid & 31, warp = tid >> 5;
    const int r = lane >> 2, c = lane & 3;
    const int mrow = warp*16 + r;    // 0..63

    const float* Qbase = Qg + (((long)b*HH + h)*QLEN + qt*64) * 64;
    const float* Kbase = Kg + ((long)b*HH + h) * KLEN * 64;
    const float* Vbase = Vg + ((long)b*HH + h) * HDIM * (long)KLEN;

    const int row0 = tid >> 4;       // 0..7
    const int u0c  = (tid & 15) * 4; // float offset of 16B chunk

    // ---- Q tile (group 0) ----
#pragma unroll
    for (int i = 0; i < 8; i++) {
        cpasync16((uint32_t)__cvta_generic_to_shared(Ps + (row0 + 8*i)*FP_LD + u0c),
                  Qbase + (row0 + 8*i)*64 + u0c);
    }
    asm volatile("cp.async.commit_group;");

    // ---- KV tile 0 (group 1) ----
    const float* kp0 = Kbase + row0*64 + u0c;
    const float* vp0 = Vbase + (long)row0*KLEN + u0c;
    const uint32_t sK0 = (uint32_t)__cvta_generic_to_shared(Kst + row0*FK_LD + u0c);
    const uint32_t sV0 = (uint32_t)__cvta_generic_to_shared(Vst + row0*FK_LD + u0c);
#pragma unroll
    for (int i = 0; i < 8; i++) {
        cpasync16(sK0 + i*(8*FK_LD*4), kp0 + i*512);
        cpasync16(sV0 + i*(8*FK_LD*4), vp0 + (long)i*8*KLEN);
    }
    asm volatile("cp.async.commit_group;");
    asm volatile("cp.async.wait_group 1;");   // Q arrived
    __syncthreads();

    // ---- extract Q A-fragments (warp-local rows) ----
    uint32_t qf[8][4];
#pragma unroll
    for (int t = 0; t < 4; t++) {
        int u0 = (c + 4*t + mrow) & 15;
        int u1 = (c + 4*t + mrow + 8) & 15;
        float4 f0 = *(const float4*)(Ps + mrow*FP_LD + u0*4);
        float4 f1 = *(const float4*)(Ps + (mrow+8)*FP_LD + u1*4);
        qf[2*t][0]   = __float_as_uint(f0.x); qf[2*t][1]   = __float_as_uint(f1.x);
        qf[2*t][2]   = __float_as_uint(f0.y); qf[2*t][3]   = __float_as_uint(f1.y);
        qf[2*t+1][0] = __float_as_uint(f0.z); qf[2*t+1][1] = __float_as_uint(f1.z);
        qf[2*t+1][2] = __float_as_uint(f0.w); qf[2*t+1][3] = __float_as_uint(f1.w);
    }

    float m_lo = -1e30f, m_hi = -1e30f, l_lo = 0.f, l_hi = 0.f;
    float o[8][4];
#pragma unroll
    for (int nj = 0; nj < 8; nj++)
#pragma unroll
        for (int i = 0; i < 4; i++) o[nj][i] = 0.f;

    const float scale = 0.125f;
    const int NT = KLEN / 64;     // 36

    for (int tt = 0; tt < NT; tt++) {
        // single barrier per iter: all warps done reading stage (tt+1)&1 (iter tt-1)
        __syncthreads();
        if (tt + 1 < NT) {
            uint32_t so = ((tt + 1) & 1) * (F_K * 4);
            const float* kg = kp0 + (tt + 1) * 4096;
            const float* vg = vp0 + (tt + 1) * 64;
#pragma unroll
            for (int i = 0; i < 8; i++) {
                cpasync16(sK0 + so + i*(8*FK_LD*4), kg + i*512);
                cpasync16(sV0 + so + i*(8*FK_LD*4), vg + (long)i*8*KLEN);
            }
        }
        asm volatile("cp.async.commit_group;");
        asm volatile("cp.async.wait_group %0;" :: "n"(1));   // tile tt ready

        const float* K0 = Kst + (tt & 1) * F_K;
        const float* V0 = Vst + (tt & 1) * F_K;

        // ---- S = Q K^T ----
        float s[8][4];
#pragma unroll
        for (int nj = 0; nj < 8; nj++)
#pragma unroll
            for (int i = 0; i < 4; i++) s[nj][i] = 0.f;

#pragma unroll
        for (int t = 0; t < 4; t++) {
#pragma unroll
            for (int nj = 0; nj < 8; nj++) {
                int row = nj*8 + r;
                int u = (c + 4*t + row) & 15;
                float4 f = *(const float4*)(K0 + row*FK_LD + u*4);
                mma_tf32(s[nj], qf[2*t],   __float_as_uint(f.x), __float_as_uint(f.y));
                mma_tf32(s[nj], qf[2*t+1], __float_as_uint(f.z), __float_as_uint(f.w));
            }
        }

        // ---- online softmax ----
        float tmax_lo = -1e30f, tmax_hi = -1e30f;
#pragma unroll
        for (int nj = 0; nj < 8; nj++) {
            s[nj][0] *= scale; s[nj][1] *= scale;
            s[nj][2] *= scale; s[nj][3] *= scale;
            tmax_lo = fmaxf(tmax_lo, fmaxf(s[nj][0], s[nj][1]));
            tmax_hi = fmaxf(tmax_hi, fmaxf(s[nj][2], s[nj][3]));
        }
        tmax_lo = fmaxf(tmax_lo, __shfl_xor_sync(0xffffffffu, tmax_lo, 1));
        tmax_hi = fmaxf(tmax_hi, __shfl_xor_sync(0xffffffffu, tmax_hi, 1));
        tmax_lo = fmaxf(tmax_lo, __shfl_xor_sync(0xffffffffu, tmax_lo, 2));
        tmax_hi = fmaxf(tmax_hi, __shfl_xor_sync(0xffffffffu, tmax_hi, 2));

        float mn_lo = fmaxf(m_lo, tmax_lo);
        float mn_hi = fmaxf(m_hi, tmax_hi);
        float corr_lo = __expf(m_lo - mn_lo);
        float corr_hi = __expf(m_hi - mn_hi);

        float ps_lo = 0.f, ps_hi = 0.f;
#pragma unroll
        for (int nj = 0; nj < 8; nj++) {
            float p0 = __expf(s[nj][0] - mn_lo);
            float p1 = __expf(s[nj][1] - mn_lo);
            float p2 = __expf(s[nj][2] - mn_hi);
            float p3 = __expf(s[nj][3] - mn_hi);
            ps_lo += p0 + p1;
            ps_hi += p2 + p3;
            int col = nj*8 + 2*c;
            float2 v0; v0.x = __uint_as_float(f2tf(p0)); v0.y = __uint_as_float(f2tf(p1));
            float2 v1; v1.x = __uint_as_float(f2tf(p2)); v1.y = __uint_as_float(f2tf(p3));
            *(float2*)(Ps + mrow*FP_LD + col) = v0;
            *(float2*)(Ps + (mrow+8)*FP_LD + col) = v1;
        }
        ps_lo += __shfl_xor_sync(0xffffffffu, ps_lo, 1);
        ps_hi += __shfl_xor_sync(0xffffffffu, ps_hi, 1);
        ps_lo += __shfl_xor_sync(0xffffffffu, ps_lo, 2);
        ps_hi += __shfl_xor_sync(0xffffffffu, ps_hi, 2);

        l_lo = l_lo*corr_lo + ps_lo;  m_lo = mn_lo;
        l_hi = l_hi*corr_hi + ps_hi;  m_hi = mn_hi;
#pragma unroll
        for (int nj = 0; nj < 8; nj++) {
            o[nj][0] *= corr_lo; o[nj][1] *= corr_lo;
            o[nj][2] *= corr_hi; o[nj][3] *= corr_hi;
        }
        __syncwarp();   // P visible to all lanes of this warp

        // ---- O += P V ----
#pragma unroll
        for (int t = 0; t < 4; t++) {
            int k0 = 16*t + c;
            int k1 = k0 + 8;
            uint32_t a0[4], a1[4];
            a0[0] = __float_as_uint(Ps[mrow*FP_LD + k0]);
            a0[1] = __float_as_uint(Ps[(mrow+8)*FP_LD + k0]);
            a0[2] = __float_as_uint(Ps[mrow*FP_LD + k0 + 4]);
            a0[3] = __float_as_uint(Ps[(mrow+8)*FP_LD + k0 + 4]);
            a1[0] = __float_as_uint(Ps[mrow*FP_LD + k1]);
            a1[1] = __float_as_uint(Ps[(mrow+8)*FP_LD + k1]);
            a1[2] = __float_as_uint(Ps[mrow*FP_LD + k1 + 4]);
            a1[3] = __float_as_uint(Ps[(mrow+8)*FP_LD + k1 + 4]);
#pragma unroll
            for (int nj = 0; nj < 8; nj++) {
                int row = nj*8 + r;
                int u = (c + 4*t + row) & 15;
                float4 f = *(const float4*)(V0 + row*FK_LD + u*4);
                mma_tf32(o[nj], a0, __float_as_uint(f.x), __float_as_uint(f.y));
                mma_tf32(o[nj], a1, __float_as_uint(f.z), __float_as_uint(f.w));
            }
        }
        __syncwarp();   // this warp done with its P rows before next-iter rewrite
    }

    // ---- normalize + write out [B, QLEN, D], tf32-rounded for out-proj ----
    float inv_lo = 1.f / l_lo;
    float inv_hi = 1.f / l_hi;
    long q0 = (long)qt*64 + warp*16 + r;
    long base_lo = ((long)b*QLEN + q0)*DD + h*HDIM;
    long base_hi = base_lo + 8L*DD;
#pragma unroll
    for (int nj = 0; nj < 8; nj++) {
        int col = nj*8 + 2*c;
        float2 v0 = make_float2(tfround(o[nj][0]*inv_lo), tfround(o[nj][1]*inv_lo));
        float2 v1 = make_float2(tfround(o[nj][2]*inv_hi), tfround(o[nj][3]*inv_hi));
        *(float2*)(Out + base_lo + col) = v0;
        *(float2*)(Out + base_hi + col) = v1;
    }
}

// ---------------- host ----------------
extern "C" void kernel_launch(void* const* d_in, const int* in_sizes, int n_in,
                              void* d_out, int out_size)
{
    const float* hs  = (const float*)d_in[0];
    const float* ehs = (const float*)d_in[1];
    const float* wq  = (const float*)d_in[2];  const float* bq  = (const float*)d_in[3];
    const float* wk  = (const float*)d_in[4];  const float* bk  = (const float*)d_in[5];
    const float* wv  = (const float*)d_in[6];  const float* bv  = (const float*)d_in[7];
    const float* awq = (const float*)d_in[8];  const float* abq = (const float*)d_in[9];
    const float* awk = (const float*)d_in[10]; const float* abk = (const float*)d_in[11];
    const float* awv = (const float*)d_in[12]; const float* abv = (const float*)d_in[13];
    const float* wo  = (const float*)d_in[14]; const float* bo  = (const float*)d_in[15];
    const float* wao = (const float*)d_in[16]; const float* bao = (const float*)d_in[17];
    float* out = (float*)d_out;

    float *wqkv, *awqkv, *wot, *waot, *hst, *ehst, *bqkv, *abqkv;
    float *qkv, *eqkv, *mq, *sq, *mk, *sk, *Qb, *Kb, *Vtb, *ao;
    cudaGetSymbolAddress((void**)&wqkv,  g_wqkv);
    cudaGetSymbolAddress((void**)&awqkv, g_awqkv);
    cudaGetSymbolAddress((void**)&wot,   g_wot);
    cudaGetSymbolAddress((void**)&waot,  g_waot);
    cudaGetSymbolAddress((void**)&hst,   g_hst);
    cudaGetSymbolAddress((void**)&ehst,  g_ehst);
    cudaGetSymbolAddress((void**)&bqkv,  g_bqkv);
    cudaGetSymbolAddress((void**)&abqkv, g_abqkv);
    cudaGetSymbolAddress((void**)&qkv,   g_qkv);
    cudaGetSymbolAddress((void**)&eqkv,  g_eqkv);
    cudaGetSymbolAddress((void**)&mq,    g_mq);
    cudaGetSymbolAddress((void**)&sq,    g_sq);
    cudaGetSymbolAddress((void**)&mk,    g_mk);
    cudaGetSymbolAddress((void**)&sk,    g_sk);
    cudaGetSymbolAddress((void**)&Qb,    g_Q);
    cudaGetSymbolAddress((void**)&Kb,    g_K);
    cudaGetSymbolAddress((void**)&Vtb,   g_Vt);
    cudaGetSymbolAddress((void**)&ao,    g_ao);

    const int M1 = BB*SS;   // 4096
    const int M2 = BB*SE;   // 1024

    cudaFuncSetAttribute(gemm_tf32_kernel,
                         cudaFuncAttributeMaxDynamicSharedMemorySize, MMA_SMEM);
    cudaFuncSetAttribute(flash3_kernel,
                         cudaFuncAttributeMaxDynamicSharedMemorySize, F_SMEM3);

    // ---- conversions (tf32 pre-rounding + concat) ----
    {
        long nw = (long)DD*D3;
        concat3_tf32_kernel<<<(unsigned)((nw + 255)/256), 256>>>(wq, wk, wv, wqkv);
        concat3_tf32_kernel<<<(unsigned)((nw + 255)/256), 256>>>(awq, awk, awv, awqkv);
        int n4;
        n4 = DD*DD/4;       cvt4_kernel<<<(n4 + 255)/256, 256>>>((const float4*)wo,  (float4*)wot,  n4);
                            cvt4_kernel<<<(n4 + 255)/256, 256>>>((const float4*)wao, (float4*)waot, n4);
        n4 = BB*SS*DD/4;    cvt4_kernel<<<(n4 + 255)/256, 256>>>((const float4*)hs,  (float4*)hst,  n4);
        n4 = BB*SE*DD/4;    cvt4_kernel<<<(n4 + 255)/256, 256>>>((const float4*)ehs, (float4*)ehst, n4);
        bias_concat_kernel<<<(D3 + 255)/256, 256>>>(bq, bk, bv, bqkv);
        bias_concat_kernel<<<(D3 + 255)/256, 256>>>(abq, abk, abv, abqkv);
    }

    // ---- fused QKV projections ----
    gemm_tf32_kernel<<<dim3(D3/TBN, M1/TBM), 256, MMA_SMEM>>>(hst,  wqkv,  bqkv,  qkv,  M1, D3, DD, M1, 0, 0);
    gemm_tf32_kernel<<<dim3(D3/TBN, M2/TBM), 256, MMA_SMEM>>>(ehst, awqkv, abqkv, eqkv, M2, D3, DD, M2, 0, 0);

    // ---- AdaIN stats ----
    stats_kernel<<<dim3(DD/256, BB), 256>>>(qkv, mq, sq, 0);
    stats_kernel<<<dim3(DD/256, BB), 256>>>(qkv, mk, sk, DD);

    // ---- build permuted Q/K/V^T ----
    {
        long tq = (long)BB*HH*QLEN*HDIM;
        long tk = (long)BB*HH*KLEN*HDIM;
        build_q_kernel<<<(unsigned)((tq + 255)/256), 256>>>(qkv, eqkv, mq, sq, Qb);
        build_k_kernel<<<(unsigned)((tk + 255)/256), 256>>>(qkv, eqkv, mk, sk, Kb);
        build_vt_kernel<<<dim3(KLEN/64, HH, BB), 256>>>(qkv, eqkv, Vtb);
    }

    // ---- flash attention (BQ=64, 128 threads, 2 CTAs/SM) ----
    flash3_kernel<<<dim3(QLEN/64, HH, BB), 128, F_SMEM3>>>(Qb, Kb, Vtb, ao);

    // ---- output projections ----
    gemm_tf32_kernel<<<dim3(DD/TBN, M1/TBM), 256, MMA_SMEM>>>(ao, wot,  bo,  out,               M1, DD, DD, SS, QLEN, 0);
    gemm_tf32_kernel<<<dim3(DD/TBN, M2/TBM), 256, MMA_SMEM>>>(ao, waot, bao, out + (long)M1*DD, M2, DD, DD, SE, QLEN, SS);
}

// round 16
// speedup vs baseline: 3.5367x; 1.0728x over previous
#include <cuda_runtime.h>
#include <cuda_bf16.h>
#include <math.h>
#include <cstdint>

// Problem constants
#define BB 4
#define SS 1024
#define SE 256
#define DD 1536
#define HH 24
#define HDIM 64
#define QLEN (SS + SE)            // 1280
#define KLEN (2*SS + SE)          // 2304
#define D3 (3*DD)                 // 4608

// ---------------- scratch (device globals; no allocs allowed) ----------------
__device__ float g_wqkv[DD*D3];       // [wq|wk|wv] tf32-rounded
__device__ float g_awqkv[DD*D3];
__device__ float g_wot[DD*DD];
__device__ float g_waot[DD*DD];
__device__ float g_hst[BB*SS*DD];     // hs tf32-rounded
__device__ float g_ehst[BB*SE*DD];
__device__ float g_bqkv[D3];
__device__ float g_abqkv[D3];
__device__ float g_qkv[BB*SS*D3];     // fused QKV projection of hs
__device__ float g_eqkv[BB*SE*D3];
__device__ float g_mq[BB*DD];
__device__ float g_sq[BB*DD];
__device__ float g_mk[BB*DD];
__device__ float g_sk[BB*DD];
__device__ float g_Q[BB*HH*QLEN*HDIM];     // d-permuted, tf32
__device__ float g_K[BB*HH*KLEN*HDIM];     // d-permuted, tf32
__device__ float g_Vt[BB*HH*HDIM*KLEN];    // transposed + k-permuted, tf32
__device__ float g_ao[BB*QLEN*DD];         // flash out, tf32-rounded

// ---------------- common helpers ----------------
__device__ __forceinline__ uint32_t f2tf(float f) {
    uint32_t r;
    asm("cvt.rna.tf32.f32 %0, %1;" : "=r"(r) : "f"(f));
    return r;
}
__device__ __forceinline__ float tfround(float f) { return __uint_as_float(f2tf(f)); }

__device__ __forceinline__ void mma_tf32(float* c, const uint32_t* a,
                                         uint32_t b0, uint32_t b1) {
    asm volatile(
        "mma.sync.aligned.m16n8k8.row.col.f32.tf32.tf32.f32 "
        "{%0,%1,%2,%3}, {%4,%5,%6,%7}, {%8,%9}, {%0,%1,%2,%3};"
        : "+f"(c[0]), "+f"(c[1]), "+f"(c[2]), "+f"(c[3])
        : "r"(a[0]), "r"(a[1]), "r"(a[2]), "r"(a[3]), "r"(b0), "r"(b1));
}

__device__ __forceinline__ void cpasync16(uint32_t saddr, const void* gptr) {
    asm volatile("cp.async.ca.shared.global [%0], [%1], 16;"
                 :: "r"(saddr), "l"(gptr));
}

// position of element k (0..63) within a permuted 64-float row; row enters mod 16
__device__ __forceinline__ int permpos(int k, int row) {
    int c   = k & 3;
    int rem = 2*(k>>3) + ((k>>2)&1);        // 0..15
    int unit = (c + (rem & ~3) + row) & 15; // (rem&~3) == 4*t
    return unit*4 + (rem & 3);
}

// ---------------- fused conversion kernel (single launch) -------------------
// All sizes in float4 units.
#define W4   (DD*D3/4)        // 1,769,472
#define WO4  (DD*DD/4)        //   589,824
#define HS4  (BB*SS*DD/4)     // 1,572,864
#define EHS4 (BB*SE*DD/4)     //   393,216
#define B4   (D3/4)           //     1,152
#define CVT_O1 (2*W4)                  // end of both qkv weight concats
#define CVT_O2 (CVT_O1 + 2*WO4)        // end of wot/waot
#define CVT_O3 (CVT_O2 + HS4)
#define CVT_O4 (CVT_O3 + EHS4)
#define CVT_TOT (CVT_O4 + 2*B4)        // 6,686,976

__global__ __launch_bounds__(256)
void cvt_all_kernel(const float4* __restrict__ wq, const float4* __restrict__ wk,
                    const float4* __restrict__ wv,
                    const float4* __restrict__ awq, const float4* __restrict__ awk,
                    const float4* __restrict__ awv,
                    const float4* __restrict__ wo, const float4* __restrict__ wao,
                    const float4* __restrict__ hs, const float4* __restrict__ ehs,
                    const float4* __restrict__ bq, const float4* __restrict__ bk,
                    const float4* __restrict__ bv,
                    const float4* __restrict__ abq, const float4* __restrict__ abk,
                    const float4* __restrict__ abv,
                    float4* __restrict__ wqkv, float4* __restrict__ awqkv,
                    float4* __restrict__ wot, float4* __restrict__ waot,
                    float4* __restrict__ hst, float4* __restrict__ ehst,
                    float4* __restrict__ bqkv, float4* __restrict__ abqkv)
{
    long u = (long)blockIdx.x*256 + threadIdx.x;
    if (u >= CVT_TOT) return;

    if (u < CVT_O1) {
        // qkv weight concat + round: dst row = uu/1152, seg = col4/384
        long uu = u; float4* d;
        const float4 *s0, *s1, *s2;
        if (uu < W4) { d = wqkv; s0 = wq; s1 = wk; s2 = wv; }
        else         { d = awqkv; s0 = awq; s1 = awk; s2 = awv; uu -= W4; }
        int row = (int)(uu / 1152), c4 = (int)(uu % 1152);
        int seg = c4 / 384;
        const float4* s = seg == 0 ? s0 : (seg == 1 ? s1 : s2);
        float4 v = s[(long)row*384 + (c4 - seg*384)];
        v.x = tfround(v.x); v.y = tfround(v.y); v.z = tfround(v.z); v.w = tfround(v.w);
        d[uu] = v;
    } else if (u < CVT_O2) {
        long uu = u - CVT_O1;
        const float4* s; float4* d;
        if (uu < WO4) { s = wo; d = wot; } else { s = wao; d = waot; uu -= WO4; }
        float4 v = s[uu];
        v.x = tfround(v.x); v.y = tfround(v.y); v.z = tfround(v.z); v.w = tfround(v.w);
        d[uu] = v;
    } else if (u < CVT_O3) {
        long uu = u - CVT_O2;
        float4 v = hs[uu];
        v.x = tfround(v.x); v.y = tfround(v.y); v.z = tfround(v.z); v.w = tfround(v.w);
        hst[uu] = v;
    } else if (u < CVT_O4) {
        long uu = u - CVT_O3;
        float4 v = ehs[uu];
        v.x = tfround(v.x); v.y = tfround(v.y); v.z = tfround(v.z); v.w = tfround(v.w);
        ehst[uu] = v;
    } else {
        // bias concats (no rounding; biases are added in f32 epilogue)
        long uu = u - CVT_O4;
        const float4 *s0, *s1, *s2; float4* d;
        if (uu < B4) { d = bqkv; s0 = bq; s1 = bk; s2 = bv; }
        else         { d = abqkv; s0 = abq; s1 = abk; s2 = abv; uu -= B4; }
        int seg = (int)(uu / 384);
        const float4* s = seg == 0 ? s0 : (seg == 1 ? s1 : s2);
        d[uu] = s[uu - seg*384];
    }
}

// ---------------- tf32 MMA GEMM (operands pre-rounded): C = A@W + bias ------
#define TBM 128
#define TBN 128
#define TBK 32
#define A_LD 36
#define B_LD 132
#define STAGE_A (TBM*A_LD)
#define STAGE_B (TBK*B_LD)
#define STAGE_SZ (STAGE_A + STAGE_B)
#define MMA_SMEM (2*STAGE_SZ*4)

__global__ __launch_bounds__(256)
void gemm_tf32_kernel(const float* __restrict__ A, const float* __restrict__ W,
                      const float* __restrict__ bias, float* __restrict__ C,
                      int M, int N, int K)
{
    extern __shared__ float smf[];

    const int tid  = threadIdx.x;
    const int lane = tid & 31;
    const int warp = tid >> 5;
    const int wm = (warp & 3) * 32;
    const int wn = (warp >> 2) * 64;
    const int mbase = blockIdx.y * TBM;
    const int nbase = blockIdx.x * TBN;

    const float* aptr[4];
    uint32_t     sA[4];
    uint32_t     sB[4];
    const float* bptr[4];
#pragma unroll
    for (int i = 0; i < 4; i++) {
        int c = tid + 256*i;
        int row = c >> 3;
        int kc  = (c & 7) * 4;
        aptr[i] = A + (long)(mbase + row) * K + kc;
        sA[i] = (uint32_t)__cvta_generic_to_shared(smf + row*A_LD + kc);

        int brow = c >> 5;
        int nc   = (c & 31) * 4;
        bptr[i] = W + (long)brow * N + nbase + nc;
        sB[i] = (uint32_t)__cvta_generic_to_shared(smf + STAGE_A + brow*B_LD + nc);
    }
    const uint32_t stage_bytes = STAGE_SZ * 4;

    float acc[2][8][4];
#pragma unroll
    for (int mi = 0; mi < 2; mi++)
#pragma unroll
        for (int nj = 0; nj < 8; nj++)
#pragma unroll
            for (int r = 0; r < 4; r++) acc[mi][nj][r] = 0.f;

    const int KT = K / TBK;

#pragma unroll
    for (int i = 0; i < 4; i++) {
        cpasync16(sA[i], aptr[i]);
        cpasync16(sB[i], bptr[i]);
    }
    asm volatile("cp.async.commit_group;");

    for (int t = 0; t < KT; t++) {
        if (t + 1 < KT) {
            int k0 = (t + 1) * TBK;
            uint32_t soff = ((t + 1) & 1) * stage_bytes;
#pragma unroll
            for (int i = 0; i < 4; i++) {
                cpasync16(sA[i] + soff, aptr[i] + k0);
                cpasync16(sB[i] + soff, bptr[i] + (long)k0 * N);
            }
        }
        asm volatile("cp.async.commit_group;");
        asm volatile("cp.async.wait_group %0;" :: "n"(1));
        __syncthreads();

        const float* As = smf + (t & 1) * STAGE_SZ;
        const float* Bs = As + STAGE_A;

#pragma unroll
        for (int kk = 0; kk < 4; kk++) {
            const int k = kk * 8;
            uint32_t af[2][4];
#pragma unroll
            for (int mi = 0; mi < 2; mi++) {
                int r = wm + mi*16 + (lane >> 2);
                int cc = k + (lane & 3);
                af[mi][0] = __float_as_uint(As[r*A_LD + cc]);
                af[mi][1] = __float_as_uint(As[(r+8)*A_LD + cc]);
                af[mi][2] = __float_as_uint(As[r*A_LD + cc + 4]);
                af[mi][3] = __float_as_uint(As[(r+8)*A_LD + cc + 4]);
            }
#pragma unroll
            for (int nj = 0; nj < 8; nj++) {
                int col = wn + nj*8 + (lane >> 2);
                uint32_t b0 = __float_as_uint(Bs[(k     + (lane & 3))*B_LD + col]);
                uint32_t b1 = __float_as_uint(Bs[(k + 4 + (lane & 3))*B_LD + col]);
                mma_tf32(acc[0][nj], af[0], b0, b1);
                mma_tf32(acc[1][nj], af[1], b0, b1);
            }
        }
        __syncthreads();
    }

#pragma unroll
    for (int mi = 0; mi < 2; mi++) {
        long row0 = mbase + wm + mi*16 + (lane >> 2);
        long row1 = row0 + 8;
#pragma unroll
        for (int nj = 0; nj < 8; nj++) {
            int col = nbase + wn + nj*8 + (lane & 3)*2;
            float b0 = bias[col], b1 = bias[col + 1];
            float2 v0 = make_float2(acc[mi][nj][0] + b0, acc[mi][nj][1] + b1);
            float2 v1 = make_float2(acc[mi][nj][2] + b0, acc[mi][nj][3] + b1);
            *(float2*)(C + row0*N + col) = v0;
            *(float2*)(C + row1*N + col) = v1;
        }
    }
}

// ---------------- fused output-projection GEMM ------------------------------
// A = g_ao (5120 x DD contiguous); 40 M-tiles; tiles (b*10+tl): tl<8 -> wo
// region (dst rows b*1024 + tl*128), tl>=8 -> wao region (dst 4096 + b*256 +
// (tl-8)*128).
__global__ __launch_bounds__(256)
void out_gemm_kernel(const float* __restrict__ A,
                     const float* __restrict__ W0, const float* __restrict__ b0v,
                     const float* __restrict__ W1, const float* __restrict__ b1v,
                     float* __restrict__ Out)
{
    extern __shared__ float smf[];

    const int tid  = threadIdx.x;
    const int lane = tid & 31;
    const int warp = tid >> 5;
    const int wm = (warp & 3) * 32;
    const int wn = (warp >> 2) * 64;
    const int by = blockIdx.y;
    const int nbase = blockIdx.x * TBN;

    const int b  = by / 10;
    const int tl = by % 10;
    const bool enc = tl >= 8;
    const float* W    = enc ? W1 : W0;
    const float* bias = enc ? b1v : b0v;
    const long dbase = enc ? (4096L + b*256 + (tl-8)*128) : ((long)b*1024 + tl*128);
    const int mbase = by * TBM;      // A row base (contiguous)

    const float* aptr[4];
    uint32_t     sA[4];
    uint32_t     sB[4];
    const float* bptr[4];
#pragma unroll
    for (int i = 0; i < 4; i++) {
        int c = tid + 256*i;
        int row = c >> 3;
        int kc  = (c & 7) * 4;
        aptr[i] = A + (long)(mbase + row) * DD + kc;
        sA[i] = (uint32_t)__cvta_generic_to_shared(smf + row*A_LD + kc);

        int brow = c >> 5;
        int nc   = (c & 31) * 4;
        bptr[i] = W + (long)brow * DD + nbase + nc;
        sB[i] = (uint32_t)__cvta_generic_to_shared(smf + STAGE_A + brow*B_LD + nc);
    }
    const uint32_t stage_bytes = STAGE_SZ * 4;

    float acc[2][8][4];
#pragma unroll
    for (int mi = 0; mi < 2; mi++)
#pragma unroll
        for (int nj = 0; nj < 8; nj++)
#pragma unroll
            for (int r = 0; r < 4; r++) acc[mi][nj][r] = 0.f;

    const int KT = DD / TBK;   // 48

#pragma unroll
    for (int i = 0; i < 4; i++) {
        cpasync16(sA[i], aptr[i]);
        cpasync16(sB[i], bptr[i]);
    }
    asm volatile("cp.async.commit_group;");

    for (int t = 0; t < KT; t++) {
        if (t + 1 < KT) {
            int k0 = (t + 1) * TBK;
            uint32_t soff = ((t + 1) & 1) * stage_bytes;
#pragma unroll
            for (int i = 0; i < 4; i++) {
                cpasync16(sA[i] + soff, aptr[i] + k0);
                cpasync16(sB[i] + soff, bptr[i] + (long)k0 * DD);
            }
        }
        asm volatile("cp.async.commit_group;");
        asm volatile("cp.async.wait_group %0;" :: "n"(1));
        __syncthreads();

        const float* As = smf + (t & 1) * STAGE_SZ;
        const float* Bs = As + STAGE_A;

#pragma unroll
        for (int kk = 0; kk < 4; kk++) {
            const int k = kk * 8;
            uint32_t af[2][4];
#pragma unroll
            for (int mi = 0; mi < 2; mi++) {
                int r = wm + mi*16 + (lane >> 2);
                int cc = k + (lane & 3);
                af[mi][0] = __float_as_uint(As[r*A_LD + cc]);
                af[mi][1] = __float_as_uint(As[(r+8)*A_LD + cc]);
                af[mi][2] = __float_as_uint(As[r*A_LD + cc + 4]);
                af[mi][3] = __float_as_uint(As[(r+8)*A_LD + cc + 4]);
            }
#pragma unroll
            for (int nj = 0; nj < 8; nj++) {
                int col = wn + nj*8 + (lane >> 2);
                uint32_t b0 = __float_as_uint(Bs[(k     + (lane & 3))*B_LD + col]);
                uint32_t b1 = __float_as_uint(Bs[(k + 4 + (lane & 3))*B_LD + col]);
                mma_tf32(acc[0][nj], af[0], b0, b1);
                mma_tf32(acc[1][nj], af[1], b0, b1);
            }
        }
        __syncthreads();
    }

#pragma unroll
    for (int mi = 0; mi < 2; mi++) {
        long row0 = dbase + wm + mi*16 + (lane >> 2);
        long row1 = row0 + 8;
#pragma unroll
        for (int nj = 0; nj < 8; nj++) {
            int col = nbase + wn + nj*8 + (lane & 3)*2;
            float bb0 = bias[col], bb1 = bias[col + 1];
            float2 v0 = make_float2(acc[mi][nj][0] + bb0, acc[mi][nj][1] + bb1);
            float2 v1 = make_float2(acc[mi][nj][2] + bb0, acc[mi][nj][3] + bb1);
            *(float2*)(Out + row0*DD + col) = v0;
            *(float2*)(Out + row1*DD + col) = v1;
        }
    }
}

// ---------------- AdaIN stats (q and k in one launch via blockIdx.z) --------
__global__ __launch_bounds__(256)
void stats_both_kernel(const float* __restrict__ X,
                       float* __restrict__ mq, float* __restrict__ sq,
                       float* __restrict__ mk, float* __restrict__ sk)
{
    int d = blockIdx.x * 256 + threadIdx.x;
    int b = blockIdx.y;
    int which = blockIdx.z;                       // 0 = q, 1 = k
    int coff = which ? DD : 0;
    float* mean = which ? mk : mq;
    float* stdv = which ? sk : sq;
    const float* p = X + (long)b*SS*D3 + coff + d;
    float s = 0.f, ss = 0.f;
    for (int i = 0; i < SS; i++) {
        float v = p[(long)i*D3];
        s += v; ss += v*v;
    }
    float mu = s * (1.f/1024.f);
    float var = (ss - 1024.f*mu*mu) * (1.f/1023.f);
    mean[b*DD + d] = mu;
    stdv[b*DD + d] = sqrtf(var + 1e-5f);
}

// ---------------- fused build kernel (Q, K, V^T in one launch) --------------
#define NQB  ((BB*HH*QLEN*HDIM)/256)     // 30720
#define NKB  ((BB*HH*KLEN*HDIM)/256)     // 55296
#define NVTB ((KLEN/64)*HH*BB)           // 3456

__global__ __launch_bounds__(256)
void build_all_kernel(const float* __restrict__ qkv, const float* __restrict__ eqkv,
                      const float* __restrict__ mq, const float* __restrict__ sq,
                      const float* __restrict__ mk, const float* __restrict__ sk,
                      float* __restrict__ Qb, float* __restrict__ Kb,
                      float* __restrict__ Vtb)
{
    __shared__ float ts[64*65];
    const int bx = blockIdx.x;
    const int tid = threadIdx.x;

    if (bx < NQB) {
        // ---- build Q ----
        long idx = (long)bx * 256 + tid;
        int hd = (int)(idx & 63);
        long t = idx >> 6;
        int p = (int)(t % QLEN); t /= QLEN;
        int h = (int)(t % HH);
        int b = (int)(t / HH);
        int d = h*HDIM + hd;
        float v;
        if (p < SS) {
            v = qkv[((long)b*SS + p)*D3 + d];
            if (b & 1) {
                int st = b - 1;
                v = (v - mq[b*DD+d]) / sq[b*DD+d] * sq[st*DD+d] + mq[st*DD+d];
            }
        } else {
            v = eqkv[((long)b*SE + (p - SS))*D3 + d];
        }
        Qb[(((long)b*HH + h)*QLEN + p)*64 + permpos(hd, p)] = tfround(v);
    } else if (bx < NQB + NKB) {
        // ---- build K ----
        long idx = (long)(bx - NQB) * 256 + tid;
        int hd = (int)(idx & 63);
        long t = idx >> 6;
        int p = (int)(t % KLEN); t /= KLEN;
        int h = (int)(t % HH);
        int b = (int)(t / HH);
        int d = h*HDIM + hd;
        float v;
        if (p < SS) {
            v = qkv[((long)b*SS + p)*D3 + DD + d];
            if (b & 1) {
                int st = b - 1;
                v = (v - mk[b*DD+d]) / sk[b*DD+d] * sk[st*DD+d] + mk[st*DD+d];
            }
        } else if (p < 2*SS) {
            int st = (b >> 1) << 1;
            v = qkv[((long)st*SS + (p - SS))*D3 + DD + d];
        } else {
            v = eqkv[((long)b*SE + (p - 2*SS))*D3 + DD + d];
        }
        Kb[(((long)b*HH + h)*KLEN + p)*64 + permpos(hd, p)] = tfround(v);
    } else {
        // ---- build V^T (smem transpose) ----
        int vtb = bx - (NQB + NKB);
        int pblk = (vtb % (KLEN/64)) * 64;
        int rest = vtb / (KLEN/64);
        int h = rest % HH;
        int b = rest / HH;
        const int hd = tid & 63;
        const int d = h*HDIM + hd;

#pragma unroll
        for (int it = 0; it < 16; it++) {
            int pl = it*4 + (tid >> 6);           // 0..63
            int p = pblk + pl;
            float v;
            if (p < SS) {
                v = qkv[((long)b*SS + p)*D3 + 2*DD + d];
            } else if (p < 2*SS) {
                int st = (b >> 1) << 1;
                v = qkv[((long)st*SS + (p - SS))*D3 + 2*DD + d];
            } else {
                v = eqkv[((long)b*SE + (p - 2*SS))*D3 + 2*DD + d];
            }
            ts[hd*65 + permpos(pl, hd)] = tfround(v);
        }
        __syncthreads();

        const int whd = tid >> 2;
        const int q = tid & 3;
        float* obase = Vtb + (((long)b*HH + h)*64 + whd)*(long)KLEN + pblk;
        const float* srow = ts + whd*65;
#pragma unroll
        for (int j = 0; j < 4; j++) {
            int unit = j*4 + q;
            float4 v;
            v.x = srow[unit*4 + 0];
            v.y = srow[unit*4 + 1];
            v.z = srow[unit*4 + 2];
            v.w = srow[unit*4 + 3];
            *(float4*)(obase + unit*4) = v;
        }
    }
}

// ---------------- Flash attention v3: 128 threads, BQ=64, occ 2 -------------
#define FP_LD 68
#define FK_LD 76
#define F_P (64*FP_LD)            // 4352 floats (Q tile, then P staging)
#define F_K (64*FK_LD)            // 4864 floats per stage
#define F_SMEM3 ((F_P + 4*F_K)*4) // 95,232 bytes -> 2 CTAs/SM

__global__ __launch_bounds__(128)
void flash3_kernel(const float* __restrict__ Qg, const float* __restrict__ Kg,
                   const float* __restrict__ Vg, float* __restrict__ Out)
{
    extern __shared__ float sm[];
    float* Ps  = sm;                 // Q tile then P staging (ld 68)
    float* Kst = sm + F_P;           // 2 stages (ld 76)
    float* Vst = Kst + 2*F_K;        // 2 stages (ld 76)

    const int qt = blockIdx.x, h = blockIdx.y, b = blockIdx.z;
    const int tid = threadIdx.x, lane = tid & 31, warp = tid >> 5;
    const int r = lane >> 2, c = lane & 3;
    const int mrow = warp*16 + r;    // 0..63

    const float* Qbase = Qg + (((long)b*HH + h)*QLEN + qt*64) * 64;
    const float* Kbase = Kg + ((long)b*HH + h) * KLEN * 64;
    const float* Vbase = Vg + ((long)b*HH + h) * HDIM * (long)KLEN;

    const int row0 = tid >> 4;       // 0..7
    const int u0c  = (tid & 15) * 4; // float offset of 16B chunk

    // ---- Q tile (group 0) ----
#pragma unroll
    for (int i = 0; i < 8; i++) {
        cpasync16((uint32_t)__cvta_generic_to_shared(Ps + (row0 + 8*i)*FP_LD + u0c),
                  Qbase + (row0 + 8*i)*64 + u0c);
    }
    asm volatile("cp.async.commit_group;");

    // ---- KV tile 0 (group 1) ----
    const float* kp0 = Kbase + row0*64 + u0c;
    const float* vp0 = Vbase + (long)row0*KLEN + u0c;
    const uint32_t sK0 = (uint32_t)__cvta_generic_to_shared(Kst + row0*FK_LD + u0c);
    const uint32_t sV0 = (uint32_t)__cvta_generic_to_shared(Vst + row0*FK_LD + u0c);
#pragma unroll
    for (int i = 0; i < 8; i++) {
        cpasync16(sK0 + i*(8*FK_LD*4), kp0 + i*512);
        cpasync16(sV0 + i*(8*FK_LD*4), vp0 + (long)i*8*KLEN);
    }
    asm volatile("cp.async.commit_group;");
    asm volatile("cp.async.wait_group 1;");   // Q arrived
    __syncthreads();

    // ---- extract Q A-fragments (warp-local rows) ----
    uint32_t qf[8][4];
#pragma unroll
    for (int t = 0; t < 4; t++) {
        int u0 = (c + 4*t + mrow) & 15;
        int u1 = (c + 4*t + mrow + 8) & 15;
        float4 f0 = *(const float4*)(Ps + mrow*FP_LD + u0*4);
        float4 f1 = *(const float4*)(Ps + (mrow+8)*FP_LD + u1*4);
        qf[2*t][0]   = __float_as_uint(f0.x); qf[2*t][1]   = __float_as_uint(f1.x);
        qf[2*t][2]   = __float_as_uint(f0.y); qf[2*t][3]   = __float_as_uint(f1.y);
        qf[2*t+1][0] = __float_as_uint(f0.z); qf[2*t+1][1] = __float_as_uint(f1.z);
        qf[2*t+1][2] = __float_as_uint(f0.w); qf[2*t+1][3] = __float_as_uint(f1.w);
    }

    float m_lo = -1e30f, m_hi = -1e30f, l_lo = 0.f, l_hi = 0.f;
    float o[8][4];
#pragma unroll
    for (int nj = 0; nj < 8; nj++)
#pragma unroll
        for (int i = 0; i < 4; i++) o[nj][i] = 0.f;

    const float scale = 0.125f;
    const int NT = KLEN / 64;     // 36

    for (int tt = 0; tt < NT; tt++) {
        // single barrier per iter: all warps done reading stage (tt+1)&1 (iter tt-1)
        __syncthreads();
        if (tt + 1 < NT) {
            uint32_t so = ((tt + 1) & 1) * (F_K * 4);
            const float* kg = kp0 + (tt + 1) * 4096;
            const float* vg = vp0 + (tt + 1) * 64;
#pragma unroll
            for (int i = 0; i < 8; i++) {
                cpasync16(sK0 + so + i*(8*FK_LD*4), kg + i*512);
                cpasync16(sV0 + so + i*(8*FK_LD*4), vg + (long)i*8*KLEN);
            }
        }
        asm volatile("cp.async.commit_group;");
        asm volatile("cp.async.wait_group %0;" :: "n"(1));   // tile tt ready

        const float* K0 = Kst + (tt & 1) * F_K;
        const float* V0 = Vst + (tt & 1) * F_K;

        // ---- S = Q K^T ----
        float s[8][4];
#pragma unroll
        for (int nj = 0; nj < 8; nj++)
#pragma unroll
            for (int i = 0; i < 4; i++) s[nj][i] = 0.f;

#pragma unroll
        for (int t = 0; t < 4; t++) {
#pragma unroll
            for (int nj = 0; nj < 8; nj++) {
                int row = nj*8 + r;
                int u = (c + 4*t + row) & 15;
                float4 f = *(const float4*)(K0 + row*FK_LD + u*4);
                mma_tf32(s[nj], qf[2*t],   __float_as_uint(f.x), __float_as_uint(f.y));
                mma_tf32(s[nj], qf[2*t+1], __float_as_uint(f.z), __float_as_uint(f.w));
            }
        }

        // ---- online softmax ----
        float tmax_lo = -1e30f, tmax_hi = -1e30f;
#pragma unroll
        for (int nj = 0; nj < 8; nj++) {
            s[nj][0] *= scale; s[nj][1] *= scale;
            s[nj][2] *= scale; s[nj][3] *= scale;
            tmax_lo = fmaxf(tmax_lo, fmaxf(s[nj][0], s[nj][1]));
            tmax_hi = fmaxf(tmax_hi, fmaxf(s[nj][2], s[nj][3]));
        }
        tmax_lo = fmaxf(tmax_lo, __shfl_xor_sync(0xffffffffu, tmax_lo, 1));
        tmax_hi = fmaxf(tmax_hi, __shfl_xor_sync(0xffffffffu, tmax_hi, 1));
        tmax_lo = fmaxf(tmax_lo, __shfl_xor_sync(0xffffffffu, tmax_lo, 2));
        tmax_hi = fmaxf(tmax_hi, __shfl_xor_sync(0xffffffffu, tmax_hi, 2));

        float mn_lo = fmaxf(m_lo, tmax_lo);
        float mn_hi = fmaxf(m_hi, tmax_hi);
        float corr_lo = __expf(m_lo - mn_lo);
        float corr_hi = __expf(m_hi - mn_hi);

        float ps_lo = 0.f, ps_hi = 0.f;
#pragma unroll
        for (int nj = 0; nj < 8; nj++) {
            float p0 = __expf(s[nj][0] - mn_lo);
            float p1 = __expf(s[nj][1] - mn_lo);
            float p2 = __expf(s[nj][2] - mn_hi);
            float p3 = __expf(s[nj][3] - mn_hi);
            ps_lo += p0 + p1;
            ps_hi += p2 + p3;
            int col = nj*8 + 2*c;
            float2 v0; v0.x = __uint_as_float(f2tf(p0)); v0.y = __uint_as_float(f2tf(p1));
            float2 v1; v1.x = __uint_as_float(f2tf(p2)); v1.y = __uint_as_float(f2tf(p3));
            *(float2*)(Ps + mrow*FP_LD + col) = v0;
            *(float2*)(Ps + (mrow+8)*FP_LD + col) = v1;
        }
        ps_lo += __shfl_xor_sync(0xffffffffu, ps_lo, 1);
        ps_hi += __shfl_xor_sync(0xffffffffu, ps_hi, 1);
        ps_lo += __shfl_xor_sync(0xffffffffu, ps_lo, 2);
        ps_hi += __shfl_xor_sync(0xffffffffu, ps_hi, 2);

        l_lo = l_lo*corr_lo + ps_lo;  m_lo = mn_lo;
        l_hi = l_hi*corr_hi + ps_hi;  m_hi = mn_hi;
#pragma unroll
        for (int nj = 0; nj < 8; nj++) {
            o[nj][0] *= corr_lo; o[nj][1] *= corr_lo;
            o[nj][2] *= corr_hi; o[nj][3] *= corr_hi;
        }
        __syncwarp();   // P visible to all lanes of this warp

        // ---- O += P V ----
#pragma unroll
        for (int t = 0; t < 4; t++) {
            int k0 = 16*t + c;
            int k1 = k0 + 8;
            uint32_t a0[4], a1[4];
            a0[0] = __float_as_uint(Ps[mrow*FP_LD + k0]);
            a0[1] = __float_as_uint(Ps[(mrow+8)*FP_LD + k0]);
            a0[2] = __float_as_uint(Ps[mrow*FP_LD + k0 + 4]);
            a0[3] = __float_as_uint(Ps[(mrow+8)*FP_LD + k0 + 4]);
            a1[0] = __float_as_uint(Ps[mrow*FP_LD + k1]);
            a1[1] = __float_as_uint(Ps[(mrow+8)*FP_LD + k1]);
            a1[2] = __float_as_uint(Ps[mrow*FP_LD + k1 + 4]);
            a1[3] = __float_as_uint(Ps[(mrow+8)*FP_LD + k1 + 4]);
#pragma unroll
            for (int nj = 0; nj < 8; nj++) {
                int row = nj*8 + r;
                int u = (c + 4*t + row) & 15;
                float4 f = *(const float4*)(V0 + row*FK_LD + u*4);
                mma_tf32(o[nj], a0, __float_as_uint(f.x), __float_as_uint(f.y));
                mma_tf32(o[nj], a1, __float_as_uint(f.z), __float_as_uint(f.w));
            }
        }
        __syncwarp();   // this warp done with its P rows before next-iter rewrite
    }

    // ---- normalize + write out [B, QLEN, D], tf32-rounded for out-proj ----
    float inv_lo = 1.f / l_lo;
    float inv_hi = 1.f / l_hi;
    long q0 = (long)qt*64 + warp*16 + r;
    long base_lo = ((long)b*QLEN + q0)*DD + h*HDIM;
    long base_hi = base_lo + 8L*DD;
#pragma unroll
    for (int nj = 0; nj < 8; nj++) {
        int col = nj*8 + 2*c;
        float2 v0 = make_float2(tfround(o[nj][0]*inv_lo), tfround(o[nj][1]*inv_lo));
        float2 v1 = make_float2(tfround(o[nj][2]*inv_hi), tfround(o[nj][3]*inv_hi));
        *(float2*)(Out + base_lo + col) = v0;
        *(float2*)(Out + base_hi + col) = v1;
    }
}

// ---------------- host ----------------
extern "C" void kernel_launch(void* const* d_in, const int* in_sizes, int n_in,
                              void* d_out, int out_size)
{
    const float* hs  = (const float*)d_in[0];
    const float* ehs = (const float*)d_in[1];
    const float* wq  = (const float*)d_in[2];  const float* bq  = (const float*)d_in[3];
    const float* wk  = (const float*)d_in[4];  const float* bk  = (const float*)d_in[5];
    const float* wv  = (const float*)d_in[6];  const float* bv  = (const float*)d_in[7];
    const float* awq = (const float*)d_in[8];  const float* abq = (const float*)d_in[9];
    const float* awk = (const float*)d_in[10]; const float* abk = (const float*)d_in[11];
    const float* awv = (const float*)d_in[12]; const float* abv = (const float*)d_in[13];
    const float* wo  = (const float*)d_in[14]; const float* bo  = (const float*)d_in[15];
    const float* wao = (const float*)d_in[16]; const float* bao = (const float*)d_in[17];
    float* out = (float*)d_out;

    float *wqkv, *awqkv, *wot, *waot, *hst, *ehst, *bqkv, *abqkv;
    float *qkv, *eqkv, *mq, *sq, *mk, *sk, *Qb, *Kb, *Vtb, *ao;
    cudaGetSymbolAddress((void**)&wqkv,  g_wqkv);
    cudaGetSymbolAddress((void**)&awqkv, g_awqkv);
    cudaGetSymbolAddress((void**)&wot,   g_wot);
    cudaGetSymbolAddress((void**)&waot,  g_waot);
    cudaGetSymbolAddress((void**)&hst,   g_hst);
    cudaGetSymbolAddress((void**)&ehst,  g_ehst);
    cudaGetSymbolAddress((void**)&bqkv,  g_bqkv);
    cudaGetSymbolAddress((void**)&abqkv, g_abqkv);
    cudaGetSymbolAddress((void**)&qkv,   g_qkv);
    cudaGetSymbolAddress((void**)&eqkv,  g_eqkv);
    cudaGetSymbolAddress((void**)&mq,    g_mq);
    cudaGetSymbolAddress((void**)&sq,    g_sq);
    cudaGetSymbolAddress((void**)&mk,    g_mk);
    cudaGetSymbolAddress((void**)&sk,    g_sk);
    cudaGetSymbolAddress((void**)&Qb,    g_Q);
    cudaGetSymbolAddress((void**)&Kb,    g_K);
    cudaGetSymbolAddress((void**)&Vtb,   g_Vt);
    cudaGetSymbolAddress((void**)&ao,    g_ao);

    const int M1 = BB*SS;   // 4096
    const int M2 = BB*SE;   // 1024

    cudaFuncSetAttribute(gemm_tf32_kernel,
                         cudaFuncAttributeMaxDynamicSharedMemorySize, MMA_SMEM);
    cudaFuncSetAttribute(out_gemm_kernel,
                         cudaFuncAttributeMaxDynamicSharedMemorySize, MMA_SMEM);
    cudaFuncSetAttribute(flash3_kernel,
                         cudaFuncAttributeMaxDynamicSharedMemorySize, F_SMEM3);

    // launch 1: all conversions fused
    cvt_all_kernel<<<(unsigned)((CVT_TOT + 255)/256), 256>>>(
        (const float4*)wq,  (const float4*)wk,  (const float4*)wv,
        (const float4*)awq, (const float4*)awk, (const float4*)awv,
        (const float4*)wo,  (const float4*)wao,
        (const float4*)hs,  (const float4*)ehs,
        (const float4*)bq,  (const float4*)bk,  (const float4*)bv,
        (const float4*)abq, (const float4*)abk, (const float4*)abv,
        (float4*)wqkv, (float4*)awqkv, (float4*)wot, (float4*)waot,
        (float4*)hst, (float4*)ehst, (float4*)bqkv, (float4*)abqkv);

    // launches 2-3: fused QKV projections
    gemm_tf32_kernel<<<dim3(D3/TBN, M1/TBM), 256, MMA_SMEM>>>(hst,  wqkv,  bqkv,  qkv,  M1, D3, DD);
    gemm_tf32_kernel<<<dim3(D3/TBN, M2/TBM), 256, MMA_SMEM>>>(ehst, awqkv, abqkv, eqkv, M2, D3, DD);

    // launch 4: AdaIN stats (q + k)
    stats_both_kernel<<<dim3(DD/256, BB, 2), 256>>>(qkv, mq, sq, mk, sk);

    // launch 5: build Q/K/V^T fused
    build_all_kernel<<<NQB + NKB + NVTB, 256>>>(qkv, eqkv, mq, sq, mk, sk, Qb, Kb, Vtb);

    // launch 6: flash attention  (profiled by ncu -s 5 -c 1)
    flash3_kernel<<<dim3(QLEN/64, HH, BB), 128, F_SMEM3>>>(Qb, Kb, Vtb, ao);

    // launch 7: fused output projections
    out_gemm_kernel<<<dim3(DD/TBN, 40), 256, MMA_SMEM>>>(ao, wot, bo, waot, bao, out);
}